// round 1
// baseline (speedup 1.0000x reference)
#include <cuda_runtime.h>
#include <math.h>

#define BSZ 2
#define SEQ 2048
#define DIM 1024
#define NH  16
#define DK  64
#define BH  (BSZ*NH)   // 32
#define MTOT (BSZ*SEQ) // 4096

// Scratch (allocation-free rule: __device__ globals)
__device__ float g_q [BSZ*SEQ*DIM];
__device__ float g_k [BSZ*SEQ*DIM];
__device__ float g_v [BSZ*SEQ*DIM];
__device__ float g_bl[BSZ*SEQ*DIM];

// ---------------------------------------------------------------------------
// C[M,N] = A[M,K] @ W[N,K]^T + bias[N]
// BM=BN=128, BK=16, 256 threads, 8x8 per thread. All dims multiples of tile.
// ---------------------------------------------------------------------------
__global__ __launch_bounds__(256) void sgemm_bias(
    const float* __restrict__ A, const float* __restrict__ W,
    const float* __restrict__ bias, float* __restrict__ C,
    int M, int N, int K)
{
    __shared__ float As[16][132];
    __shared__ float Ws[16][132];
    int tid = threadIdx.x;
    int tx = tid & 15, ty = tid >> 4;
    const float* Ablk = A + (size_t)(blockIdx.y * 128) * K;
    const float* Wblk = W + (size_t)(blockIdx.x * 128) * K;
    float acc[8][8] = {};

    for (int k0 = 0; k0 < K; k0 += 16) {
        #pragma unroll
        for (int i = 0; i < 2; i++) {
            int id = tid + i * 256;
            int r  = id >> 2;
            int c  = (id & 3) << 2;
            float4 va = *(const float4*)(Ablk + (size_t)r * K + k0 + c);
            As[c+0][r] = va.x; As[c+1][r] = va.y; As[c+2][r] = va.z; As[c+3][r] = va.w;
            float4 vw = *(const float4*)(Wblk + (size_t)r * K + k0 + c);
            Ws[c+0][r] = vw.x; Ws[c+1][r] = vw.y; Ws[c+2][r] = vw.z; Ws[c+3][r] = vw.w;
        }
        __syncthreads();
        #pragma unroll
        for (int kk = 0; kk < 16; kk++) {
            float a[8], w[8];
            *(float4*)&a[0] = *(const float4*)&As[kk][ty * 8];
            *(float4*)&a[4] = *(const float4*)&As[kk][ty * 8 + 4];
            *(float4*)&w[0] = *(const float4*)&Ws[kk][tx * 8];
            *(float4*)&w[4] = *(const float4*)&Ws[kk][tx * 8 + 4];
            #pragma unroll
            for (int i = 0; i < 8; i++)
                #pragma unroll
                for (int j = 0; j < 8; j++)
                    acc[i][j] += a[i] * w[j];
        }
        __syncthreads();
    }

    int row0 = blockIdx.y * 128 + ty * 8;
    int col0 = blockIdx.x * 128 + tx * 8;
    float bb[8];
    *(float4*)&bb[0] = *(const float4*)&bias[col0];
    *(float4*)&bb[4] = *(const float4*)&bias[col0 + 4];
    float* Cb = C + (size_t)row0 * N + col0;
    #pragma unroll
    for (int i = 0; i < 8; i++) {
        float4 o0 = make_float4(acc[i][0]+bb[0], acc[i][1]+bb[1], acc[i][2]+bb[2], acc[i][3]+bb[3]);
        float4 o1 = make_float4(acc[i][4]+bb[4], acc[i][5]+bb[5], acc[i][6]+bb[6], acc[i][7]+bb[7]);
        *(float4*)(Cb + (size_t)i * N)     = o0;
        *(float4*)(Cb + (size_t)i * N + 4) = o1;
    }
}

// ---------------------------------------------------------------------------
// Raw scaled scores: score[bh, sq, sk] = (1/8) * sum_d q[b,sq,h*64+d]*k[b,sk,h*64+d]
// grid (SEQ/128 key tiles, SEQ/128 query tiles, BH)
// ---------------------------------------------------------------------------
__global__ __launch_bounds__(256) void attn_scores(float* __restrict__ score)
{
    __shared__ float Qs[16][132];
    __shared__ float Ks[16][132];
    int tid = threadIdx.x;
    int tx = tid & 15, ty = tid >> 4;
    int bh = blockIdx.z;
    int b = bh >> 4, h = bh & 15;

    const float* qb = g_q + (size_t)b * SEQ * DIM + (size_t)(blockIdx.y * 128) * DIM + h * DK;
    const float* kb = g_k + (size_t)b * SEQ * DIM + (size_t)(blockIdx.x * 128) * DIM + h * DK;
    float acc[8][8] = {};

    for (int k0 = 0; k0 < DK; k0 += 16) {
        #pragma unroll
        for (int i = 0; i < 2; i++) {
            int id = tid + i * 256;
            int r  = id >> 2;
            int c  = (id & 3) << 2;
            float4 va = *(const float4*)(qb + (size_t)r * DIM + k0 + c);
            Qs[c+0][r] = va.x; Qs[c+1][r] = va.y; Qs[c+2][r] = va.z; Qs[c+3][r] = va.w;
            float4 vk = *(const float4*)(kb + (size_t)r * DIM + k0 + c);
            Ks[c+0][r] = vk.x; Ks[c+1][r] = vk.y; Ks[c+2][r] = vk.z; Ks[c+3][r] = vk.w;
        }
        __syncthreads();
        #pragma unroll
        for (int kk = 0; kk < 16; kk++) {
            float a[8], w[8];
            *(float4*)&a[0] = *(const float4*)&Qs[kk][ty * 8];
            *(float4*)&a[4] = *(const float4*)&Qs[kk][ty * 8 + 4];
            *(float4*)&w[0] = *(const float4*)&Ks[kk][tx * 8];
            *(float4*)&w[4] = *(const float4*)&Ks[kk][tx * 8 + 4];
            #pragma unroll
            for (int i = 0; i < 8; i++)
                #pragma unroll
                for (int j = 0; j < 8; j++)
                    acc[i][j] += a[i] * w[j];
        }
        __syncthreads();
    }

    const float alpha = 0.125f;  // 1/sqrt(64)
    float* ob = score + (size_t)bh * SEQ * SEQ
              + (size_t)(blockIdx.y * 128 + ty * 8) * SEQ
              + blockIdx.x * 128 + tx * 8;
    #pragma unroll
    for (int i = 0; i < 8; i++) {
        float4 o0 = make_float4(acc[i][0]*alpha, acc[i][1]*alpha, acc[i][2]*alpha, acc[i][3]*alpha);
        float4 o1 = make_float4(acc[i][4]*alpha, acc[i][5]*alpha, acc[i][6]*alpha, acc[i][7]*alpha);
        *(float4*)(ob + (size_t)i * SEQ)     = o0;
        *(float4*)(ob + (size_t)i * SEQ + 4) = o1;
    }
}

// ---------------------------------------------------------------------------
// In-place row softmax over last dim (SEQ=2048). One block per row, 256 thr,
// 8 contiguous floats per thread.
// ---------------------------------------------------------------------------
__global__ __launch_bounds__(256) void softmax_rows(float* __restrict__ score)
{
    size_t row = blockIdx.x;
    float* p = score + row * SEQ;
    int tid = threadIdx.x;
    __shared__ float red[256];

    float4 x0 = ((const float4*)p)[tid * 2];
    float4 x1 = ((const float4*)p)[tid * 2 + 1];

    float m = fmaxf(fmaxf(fmaxf(x0.x, x0.y), fmaxf(x0.z, x0.w)),
                    fmaxf(fmaxf(x1.x, x1.y), fmaxf(x1.z, x1.w)));
    red[tid] = m;
    __syncthreads();
    for (int s = 128; s > 0; s >>= 1) {
        if (tid < s) red[tid] = fmaxf(red[tid], red[tid + s]);
        __syncthreads();
    }
    m = red[0];
    __syncthreads();

    float4 e0, e1;
    e0.x = __expf(x0.x - m); e0.y = __expf(x0.y - m);
    e0.z = __expf(x0.z - m); e0.w = __expf(x0.w - m);
    e1.x = __expf(x1.x - m); e1.y = __expf(x1.y - m);
    e1.z = __expf(x1.z - m); e1.w = __expf(x1.w - m);

    float s8 = (e0.x + e0.y + e0.z + e0.w) + (e1.x + e1.y + e1.z + e1.w);
    red[tid] = s8;
    __syncthreads();
    for (int s = 128; s > 0; s >>= 1) {
        if (tid < s) red[tid] += red[tid + s];
        __syncthreads();
    }
    float inv = 1.0f / red[0];

    e0.x *= inv; e0.y *= inv; e0.z *= inv; e0.w *= inv;
    e1.x *= inv; e1.y *= inv; e1.z *= inv; e1.w *= inv;
    ((float4*)p)[tid * 2]     = e0;
    ((float4*)p)[tid * 2 + 1] = e1;
}

// ---------------------------------------------------------------------------
// blended[b,sq,h*64+d] = sum_t p[bh,sq,t] * v[b,t,h*64+d]
// grid (SEQ/128 query tiles, BH). BM=128, BN=64, BK=16, 8x4 per thread.
// ---------------------------------------------------------------------------
__global__ __launch_bounds__(256) void attn_pv(const float* __restrict__ score)
{
    __shared__ float Ps[16][132];
    __shared__ float Vs[16][64];
    int tid = threadIdx.x;
    int tx = tid & 15, ty = tid >> 4;
    int bh = blockIdx.y;
    int b = bh >> 4, h = bh & 15;

    const float* pb = score + (size_t)bh * SEQ * SEQ + (size_t)(blockIdx.x * 128) * SEQ;
    const float* vb = g_v + (size_t)b * SEQ * DIM + h * DK;
    float acc[8][4] = {};

    for (int k0 = 0; k0 < SEQ; k0 += 16) {
        #pragma unroll
        for (int i = 0; i < 2; i++) {
            int id = tid + i * 256;
            int r  = id >> 2;
            int c  = (id & 3) << 2;
            float4 vp = *(const float4*)(pb + (size_t)r * SEQ + k0 + c);
            Ps[c+0][r] = vp.x; Ps[c+1][r] = vp.y; Ps[c+2][r] = vp.z; Ps[c+3][r] = vp.w;
        }
        {
            int r = tid >> 4;          // 0..15 (k within tile)
            int c = (tid & 15) << 2;   // 0..60
            float4 vv = *(const float4*)(vb + (size_t)(k0 + r) * DIM + c);
            *(float4*)&Vs[r][c] = vv;
        }
        __syncthreads();
        #pragma unroll
        for (int kk = 0; kk < 16; kk++) {
            float a[8], w[4];
            *(float4*)&a[0] = *(const float4*)&Ps[kk][ty * 8];
            *(float4*)&a[4] = *(const float4*)&Ps[kk][ty * 8 + 4];
            *(float4*)&w[0] = *(const float4*)&Vs[kk][tx * 4];
            #pragma unroll
            for (int i = 0; i < 8; i++)
                #pragma unroll
                for (int j = 0; j < 4; j++)
                    acc[i][j] += a[i] * w[j];
        }
        __syncthreads();
    }

    float* ob = g_bl + (size_t)b * SEQ * DIM
              + (size_t)(blockIdx.x * 128 + ty * 8) * DIM + h * DK + tx * 4;
    #pragma unroll
    for (int i = 0; i < 8; i++) {
        float4 o = make_float4(acc[i][0], acc[i][1], acc[i][2], acc[i][3]);
        *(float4*)(ob + (size_t)i * DIM) = o;
    }
}

// ---------------------------------------------------------------------------
extern "C" void kernel_launch(void* const* d_in, const int* in_sizes, int n_in,
                              void* d_out, int out_size)
{
    const float* query = (const float*)d_in[0];
    const float* key   = (const float*)d_in[1];
    const float* value = (const float*)d_in[2];
    const float* Wq    = (const float*)d_in[3];
    const float* bq    = (const float*)d_in[4];
    const float* Wk    = (const float*)d_in[5];
    const float* bk    = (const float*)d_in[6];
    const float* Wv    = (const float*)d_in[7];
    const float* bv    = (const float*)d_in[8];
    const float* Wo    = (const float*)d_in[9];
    const float* bo    = (const float*)d_in[10];

    float* out   = (float*)d_out;                          // [B,S,D]
    float* score = out + (size_t)BSZ * SEQ * DIM;          // [B,H,S,S]

    float *pq, *pk, *pv, *pbl;
    cudaGetSymbolAddress((void**)&pq,  g_q);
    cudaGetSymbolAddress((void**)&pk,  g_k);
    cudaGetSymbolAddress((void**)&pv,  g_v);
    cudaGetSymbolAddress((void**)&pbl, g_bl);

    dim3 gp(DIM / 128, MTOT / 128);   // (8, 32)
    sgemm_bias<<<gp, 256>>>(query, Wq, bq, pq, MTOT, DIM, DIM);
    sgemm_bias<<<gp, 256>>>(key,   Wk, bk, pk, MTOT, DIM, DIM);
    sgemm_bias<<<gp, 256>>>(value, Wv, bv, pv, MTOT, DIM, DIM);

    attn_scores<<<dim3(SEQ / 128, SEQ / 128, BH), 256>>>(score);
    softmax_rows<<<BH * SEQ, 256>>>(score);
    attn_pv<<<dim3(SEQ / 128, BH), 256>>>(score);

    sgemm_bias<<<gp, 256>>>(pbl, Wo, bo, out, MTOT, DIM, DIM);
}

// round 2
// speedup vs baseline: 1.7051x; 1.7051x over previous
#include <cuda_runtime.h>
#include <math.h>

#define BSZ 2
#define SEQ 2048
#define DIM 1024
#define NH  16
#define DK  64
#define BH  (BSZ*NH)   // 32
#define MTOT (BSZ*SEQ) // 4096

// Scratch (allocation-free rule: __device__ globals)
__device__ float g_q [BSZ*SEQ*DIM];
__device__ float g_k [BSZ*SEQ*DIM];
__device__ float g_v [BSZ*SEQ*DIM];
__device__ float g_bl[BSZ*SEQ*DIM];

// ---------------------------------------------------------------------------
// tf32 helpers
// ---------------------------------------------------------------------------
__device__ __forceinline__ unsigned f2tf(float x) {
    unsigned r;
    asm("cvt.rna.tf32.f32 %0, %1;" : "=r"(r) : "f"(x));
    return r;
}

__device__ __forceinline__ void mma_tf32(float c[4],
    unsigned a0, unsigned a1, unsigned a2, unsigned a3,
    unsigned b0, unsigned b1)
{
    asm volatile(
        "mma.sync.aligned.m16n8k8.row.col.f32.tf32.tf32.f32 "
        "{%0,%1,%2,%3}, {%4,%5,%6,%7}, {%8,%9}, {%0,%1,%2,%3};\n"
        : "+f"(c[0]), "+f"(c[1]), "+f"(c[2]), "+f"(c[3])
        : "r"(a0), "r"(a1), "r"(a2), "r"(a3), "r"(b0), "r"(b1));
}

// Load a 128x16 tile (row-major src, row stride lda) transposed into
// dst[k][m] (stride 136 => conflict-free fragment LDS), values tf32-rounded.
__device__ __forceinline__ void load_tile_T(
    const float* __restrict__ src, int lda, unsigned (*dst)[136], int tid)
{
    #pragma unroll
    for (int i = 0; i < 2; i++) {
        int id = tid + i * 256;
        int r  = id >> 2;
        int c  = (id & 3) << 2;
        float4 v = *(const float4*)(src + (size_t)r * lda + c);
        dst[c+0][r] = f2tf(v.x);
        dst[c+1][r] = f2tf(v.y);
        dst[c+2][r] = f2tf(v.z);
        dst[c+3][r] = f2tf(v.w);
    }
}

// 128x128 block mainloop: A[M,K] (lda) x B-rows[N,K] (ldb), nk k-tiles of 16.
// Warp layout: 2 (M) x 4 (N), warp tile 64x32, 4x4 m16n8 fragments.
__device__ __forceinline__ void mma_loop_128x128(
    const float* __restrict__ A, int lda,
    const float* __restrict__ B, int ldb, int nk,
    unsigned (*As)[136], unsigned (*Bs)[136],
    float acc[4][4][4], int tid)
{
    int warp = tid >> 5, lane = tid & 31;
    int wm = warp >> 2, wn = warp & 3;
    int grp = lane >> 2, qd = lane & 3;

    for (int t = 0; t < nk; t++) {
        load_tile_T(A + t * 16, lda, As, tid);
        load_tile_T(B + t * 16, ldb, Bs, tid);
        __syncthreads();
        #pragma unroll
        for (int kk = 0; kk < 16; kk += 8) {
            unsigned a[4][4], bfr[4][2];
            #pragma unroll
            for (int mi = 0; mi < 4; mi++) {
                int m = wm * 64 + mi * 16;
                a[mi][0] = As[kk + qd    ][m + grp    ];
                a[mi][1] = As[kk + qd    ][m + grp + 8];
                a[mi][2] = As[kk + qd + 4][m + grp    ];
                a[mi][3] = As[kk + qd + 4][m + grp + 8];
            }
            #pragma unroll
            for (int ni = 0; ni < 4; ni++) {
                int n = wn * 32 + ni * 8;
                bfr[ni][0] = Bs[kk + qd    ][n + grp];
                bfr[ni][1] = Bs[kk + qd + 4][n + grp];
            }
            #pragma unroll
            for (int mi = 0; mi < 4; mi++)
                #pragma unroll
                for (int ni = 0; ni < 4; ni++)
                    mma_tf32(acc[mi][ni], a[mi][0], a[mi][1], a[mi][2], a[mi][3],
                             bfr[ni][0], bfr[ni][1]);
        }
        __syncthreads();
    }
}

// ---------------------------------------------------------------------------
// C[M,N] = A[M,K] @ W[N,K]^T + bias[N]
// ---------------------------------------------------------------------------
__global__ __launch_bounds__(256, 2) void gemm_tf32_bias(
    const float* __restrict__ A, const float* __restrict__ W,
    const float* __restrict__ bias, float* __restrict__ C,
    int M, int N, int K)
{
    __shared__ unsigned As[16][136];
    __shared__ unsigned Bs[16][136];
    int tid = threadIdx.x;
    const float* Ab = A + (size_t)(blockIdx.y * 128) * K;
    const float* Wb = W + (size_t)(blockIdx.x * 128) * K;
    float acc[4][4][4] = {};
    mma_loop_128x128(Ab, K, Wb, K, K / 16, As, Bs, acc, tid);

    int warp = tid >> 5, lane = tid & 31;
    int wm = warp >> 2, wn = warp & 3;
    int grp = lane >> 2, qd = lane & 3;
    int row0 = blockIdx.y * 128 + wm * 64;
    int col0 = blockIdx.x * 128 + wn * 32;
    #pragma unroll
    for (int mi = 0; mi < 4; mi++) {
        #pragma unroll
        for (int ni = 0; ni < 4; ni++) {
            int r  = row0 + mi * 16 + grp;
            int cc = col0 + ni * 8 + qd * 2;
            float b0 = bias[cc], b1 = bias[cc + 1];
            *(float2*)(C + (size_t)r * N + cc) =
                make_float2(acc[mi][ni][0] + b0, acc[mi][ni][1] + b1);
            *(float2*)(C + (size_t)(r + 8) * N + cc) =
                make_float2(acc[mi][ni][2] + b0, acc[mi][ni][3] + b1);
        }
    }
}

// ---------------------------------------------------------------------------
// score[bh, sq, sk] = (1/8) * q . k
// ---------------------------------------------------------------------------
__global__ __launch_bounds__(256, 2) void attn_scores_tf32(float* __restrict__ score)
{
    __shared__ unsigned As[16][136];
    __shared__ unsigned Bs[16][136];
    int tid = threadIdx.x;
    int bh = blockIdx.z, b = bh >> 4, h = bh & 15;
    const float* qb = g_q + (size_t)b * SEQ * DIM + (size_t)(blockIdx.y * 128) * DIM + h * DK;
    const float* kb = g_k + (size_t)b * SEQ * DIM + (size_t)(blockIdx.x * 128) * DIM + h * DK;
    float acc[4][4][4] = {};
    mma_loop_128x128(qb, DIM, kb, DIM, DK / 16, As, Bs, acc, tid);

    int warp = tid >> 5, lane = tid & 31;
    int wm = warp >> 2, wn = warp & 3;
    int grp = lane >> 2, qd = lane & 3;
    const float alpha = 0.125f;
    float* ob = score + (size_t)bh * SEQ * SEQ;
    int row0 = blockIdx.y * 128 + wm * 64;
    int col0 = blockIdx.x * 128 + wn * 32;
    #pragma unroll
    for (int mi = 0; mi < 4; mi++) {
        #pragma unroll
        for (int ni = 0; ni < 4; ni++) {
            int r  = row0 + mi * 16 + grp;
            int cc = col0 + ni * 8 + qd * 2;
            *(float2*)(ob + (size_t)r * SEQ + cc) =
                make_float2(acc[mi][ni][0] * alpha, acc[mi][ni][1] * alpha);
            *(float2*)(ob + (size_t)(r + 8) * SEQ + cc) =
                make_float2(acc[mi][ni][2] * alpha, acc[mi][ni][3] * alpha);
        }
    }
}

// ---------------------------------------------------------------------------
// In-place row softmax over last dim (SEQ=2048). One block per row.
// ---------------------------------------------------------------------------
__global__ __launch_bounds__(256) void softmax_rows(float* __restrict__ score)
{
    size_t row = blockIdx.x;
    float* p = score + row * SEQ;
    int tid = threadIdx.x;
    __shared__ float red[256];

    float4 x0 = ((const float4*)p)[tid * 2];
    float4 x1 = ((const float4*)p)[tid * 2 + 1];

    float m = fmaxf(fmaxf(fmaxf(x0.x, x0.y), fmaxf(x0.z, x0.w)),
                    fmaxf(fmaxf(x1.x, x1.y), fmaxf(x1.z, x1.w)));
    red[tid] = m;
    __syncthreads();
    for (int s = 128; s > 0; s >>= 1) {
        if (tid < s) red[tid] = fmaxf(red[tid], red[tid + s]);
        __syncthreads();
    }
    m = red[0];
    __syncthreads();

    float4 e0, e1;
    e0.x = __expf(x0.x - m); e0.y = __expf(x0.y - m);
    e0.z = __expf(x0.z - m); e0.w = __expf(x0.w - m);
    e1.x = __expf(x1.x - m); e1.y = __expf(x1.y - m);
    e1.z = __expf(x1.z - m); e1.w = __expf(x1.w - m);

    float s8 = (e0.x + e0.y + e0.z + e0.w) + (e1.x + e1.y + e1.z + e1.w);
    red[tid] = s8;
    __syncthreads();
    for (int s = 128; s > 0; s >>= 1) {
        if (tid < s) red[tid] += red[tid + s];
        __syncthreads();
    }
    float inv = 1.0f / red[0];

    e0.x *= inv; e0.y *= inv; e0.z *= inv; e0.w *= inv;
    e1.x *= inv; e1.y *= inv; e1.z *= inv; e1.w *= inv;
    ((float4*)p)[tid * 2]     = e0;
    ((float4*)p)[tid * 2 + 1] = e1;
}

// ---------------------------------------------------------------------------
// blended[b,sq,h*64+d] = sum_t p[bh,sq,t] * v[b,t,h*64+d]
// Tile 128x64, K=2048. Warps 4(M) x 2(N), warp tile 32x32.
// ---------------------------------------------------------------------------
__global__ __launch_bounds__(256, 2) void attn_pv_tf32(const float* __restrict__ score)
{
    __shared__ unsigned Ps[16][136];
    __shared__ unsigned Vs[16][72];
    int tid = threadIdx.x;
    int bh = blockIdx.y, b = bh >> 4, h = bh & 15;
    const float* pb = score + (size_t)bh * SEQ * SEQ + (size_t)(blockIdx.x * 128) * SEQ;
    const float* vb = g_v + (size_t)b * SEQ * DIM + h * DK;

    int warp = tid >> 5, lane = tid & 31;
    int wm = warp >> 1, wn = warp & 1;
    int grp = lane >> 2, qd = lane & 3;
    float acc[2][4][4] = {};

    for (int t = 0; t < SEQ / 16; t++) {
        load_tile_T(pb + t * 16, SEQ, Ps, tid);
        {
            int r = tid >> 4;           // 0..15 (k)
            int c = (tid & 15) << 2;    // 0..60 (n)
            float4 v = *(const float4*)(vb + (size_t)(t * 16 + r) * DIM + c);
            Vs[r][c+0] = f2tf(v.x);
            Vs[r][c+1] = f2tf(v.y);
            Vs[r][c+2] = f2tf(v.z);
            Vs[r][c+3] = f2tf(v.w);
        }
        __syncthreads();
        #pragma unroll
        for (int kk = 0; kk < 16; kk += 8) {
            unsigned a[2][4], bfr[4][2];
            #pragma unroll
            for (int mi = 0; mi < 2; mi++) {
                int m = wm * 32 + mi * 16;
                a[mi][0] = Ps[kk + qd    ][m + grp    ];
                a[mi][1] = Ps[kk + qd    ][m + grp + 8];
                a[mi][2] = Ps[kk + qd + 4][m + grp    ];
                a[mi][3] = Ps[kk + qd + 4][m + grp + 8];
            }
            #pragma unroll
            for (int ni = 0; ni < 4; ni++) {
                int n = wn * 32 + ni * 8;
                bfr[ni][0] = Vs[kk + qd    ][n + grp];
                bfr[ni][1] = Vs[kk + qd + 4][n + grp];
            }
            #pragma unroll
            for (int mi = 0; mi < 2; mi++)
                #pragma unroll
                for (int ni = 0; ni < 4; ni++)
                    mma_tf32(acc[mi][ni], a[mi][0], a[mi][1], a[mi][2], a[mi][3],
                             bfr[ni][0], bfr[ni][1]);
        }
        __syncthreads();
    }

    int row0 = blockIdx.x * 128 + wm * 32;
    int col0 = h * DK + wn * 32;
    float* ob = g_bl + (size_t)b * SEQ * DIM;
    #pragma unroll
    for (int mi = 0; mi < 2; mi++) {
        #pragma unroll
        for (int ni = 0; ni < 4; ni++) {
            int r  = row0 + mi * 16 + grp;
            int cc = col0 + ni * 8 + qd * 2;
            *(float2*)(ob + (size_t)r * DIM + cc) =
                make_float2(acc[mi][ni][0], acc[mi][ni][1]);
            *(float2*)(ob + (size_t)(r + 8) * DIM + cc) =
                make_float2(acc[mi][ni][2], acc[mi][ni][3]);
        }
    }
}

// ---------------------------------------------------------------------------
extern "C" void kernel_launch(void* const* d_in, const int* in_sizes, int n_in,
                              void* d_out, int out_size)
{
    const float* query = (const float*)d_in[0];
    const float* key   = (const float*)d_in[1];
    const float* value = (const float*)d_in[2];
    const float* Wq    = (const float*)d_in[3];
    const float* bq    = (const float*)d_in[4];
    const float* Wk    = (const float*)d_in[5];
    const float* bk    = (const float*)d_in[6];
    const float* Wv    = (const float*)d_in[7];
    const float* bv    = (const float*)d_in[8];
    const float* Wo    = (const float*)d_in[9];
    const float* bo    = (const float*)d_in[10];

    float* out   = (float*)d_out;                          // [B,S,D]
    float* score = out + (size_t)BSZ * SEQ * DIM;          // [B,H,S,S]

    float *pq, *pk, *pv, *pbl;
    cudaGetSymbolAddress((void**)&pq,  g_q);
    cudaGetSymbolAddress((void**)&pk,  g_k);
    cudaGetSymbolAddress((void**)&pv,  g_v);
    cudaGetSymbolAddress((void**)&pbl, g_bl);

    dim3 gp(DIM / 128, MTOT / 128);   // (8, 32)
    gemm_tf32_bias<<<gp, 256>>>(query, Wq, bq, pq, MTOT, DIM, DIM);
    gemm_tf32_bias<<<gp, 256>>>(key,   Wk, bk, pk, MTOT, DIM, DIM);
    gemm_tf32_bias<<<gp, 256>>>(value, Wv, bv, pv, MTOT, DIM, DIM);

    attn_scores_tf32<<<dim3(SEQ / 128, SEQ / 128, BH), 256>>>(score);
    softmax_rows<<<BH * SEQ, 256>>>(score);
    attn_pv_tf32<<<dim3(SEQ / 128, BH), 256>>>(score);

    gemm_tf32_bias<<<gp, 256>>>(pbl, Wo, bo, out, MTOT, DIM, DIM);
}

// round 3
// speedup vs baseline: 1.9754x; 1.1585x over previous
#include <cuda_runtime.h>
#include <math.h>

#define BSZ 2
#define SEQ 2048
#define DIM 1024
#define NH  16
#define DK  64
#define BH  (BSZ*NH)   // 32
#define MTOT (BSZ*SEQ) // 4096

// Scratch (allocation-free rule: __device__ globals)
__device__ float g_q [BSZ*SEQ*DIM];
__device__ float g_k [BSZ*SEQ*DIM];
__device__ float g_v [BSZ*SEQ*DIM];
__device__ float g_bl[BSZ*SEQ*DIM];

// ---------------------------------------------------------------------------
// tf32 helpers
// ---------------------------------------------------------------------------
__device__ __forceinline__ unsigned f2tf(float x) {
    unsigned r;
    asm("cvt.rna.tf32.f32 %0, %1;" : "=r"(r) : "f"(x));
    return r;
}

__device__ __forceinline__ void mma_tf32(float c[4],
    unsigned a0, unsigned a1, unsigned a2, unsigned a3,
    unsigned b0, unsigned b1)
{
    asm volatile(
        "mma.sync.aligned.m16n8k8.row.col.f32.tf32.tf32.f32 "
        "{%0,%1,%2,%3}, {%4,%5,%6,%7}, {%8,%9}, {%0,%1,%2,%3};\n"
        : "+f"(c[0]), "+f"(c[1]), "+f"(c[2]), "+f"(c[3])
        : "r"(a0), "r"(a1), "r"(a2), "r"(a3), "r"(b0), "r"(b1));
}

// Global 128x16 tile load into registers (2 float4 / thread).
__device__ __forceinline__ void ldg_tile(
    const float* __restrict__ src, int lda, int tid, float4 v[2])
{
    #pragma unroll
    for (int i = 0; i < 2; i++) {
        int id = tid + i * 256;
        int r  = id >> 2;
        int c  = (id & 3) << 2;
        v[i] = *(const float4*)(src + (size_t)r * lda + c);
    }
}

// Store register tile transposed into smem dst[k][m] with tf32 rounding.
__device__ __forceinline__ void sts_tile(
    unsigned (*dst)[136], int tid, const float4 v[2])
{
    #pragma unroll
    for (int i = 0; i < 2; i++) {
        int id = tid + i * 256;
        int r  = id >> 2;
        int c  = (id & 3) << 2;
        dst[c+0][r] = f2tf(v[i].x);
        dst[c+1][r] = f2tf(v[i].y);
        dst[c+2][r] = f2tf(v[i].z);
        dst[c+3][r] = f2tf(v[i].w);
    }
}

// Double-buffered 128x128 mainloop. Warps 2(M) x 4(N), warp tile 64x32.
__device__ __forceinline__ void mma_loop_128x128_db(
    const float* __restrict__ A, int lda,
    const float* __restrict__ B, int ldb, int nk,
    unsigned (*As)[16][136], unsigned (*Bs)[16][136],
    float acc[4][4][4], int tid)
{
    int warp = tid >> 5, lane = tid & 31;
    int wm = warp >> 2, wn = warp & 3;
    int grp = lane >> 2, qd = lane & 3;

    float4 pa[2], pb[2];
    ldg_tile(A, lda, tid, pa);
    ldg_tile(B, ldb, tid, pb);
    sts_tile(As[0], tid, pa);
    sts_tile(Bs[0], tid, pb);
    __syncthreads();

    for (int t = 0; t < nk; t++) {
        int cur = t & 1;
        if (t + 1 < nk) {
            ldg_tile(A + (t + 1) * 16, lda, tid, pa);
            ldg_tile(B + (t + 1) * 16, ldb, tid, pb);
        }
        #pragma unroll
        for (int kk = 0; kk < 16; kk += 8) {
            unsigned a[4][4], bfr[4][2];
            #pragma unroll
            for (int mi = 0; mi < 4; mi++) {
                int m = wm * 64 + mi * 16;
                a[mi][0] = As[cur][kk + qd    ][m + grp    ];
                a[mi][1] = As[cur][kk + qd    ][m + grp + 8];
                a[mi][2] = As[cur][kk + qd + 4][m + grp    ];
                a[mi][3] = As[cur][kk + qd + 4][m + grp + 8];
            }
            #pragma unroll
            for (int ni = 0; ni < 4; ni++) {
                int n = wn * 32 + ni * 8;
                bfr[ni][0] = Bs[cur][kk + qd    ][n + grp];
                bfr[ni][1] = Bs[cur][kk + qd + 4][n + grp];
            }
            #pragma unroll
            for (int mi = 0; mi < 4; mi++)
                #pragma unroll
                for (int ni = 0; ni < 4; ni++)
                    mma_tf32(acc[mi][ni], a[mi][0], a[mi][1], a[mi][2], a[mi][3],
                             bfr[ni][0], bfr[ni][1]);
        }
        if (t + 1 < nk) {
            sts_tile(As[cur ^ 1], tid, pa);
            sts_tile(Bs[cur ^ 1], tid, pb);
            __syncthreads();
        }
    }
}

// ---------------------------------------------------------------------------
// C[M,N] = A[M,K] @ W[N,K]^T + bias[N]
// ---------------------------------------------------------------------------
__global__ __launch_bounds__(256, 2) void gemm_tf32_bias(
    const float* __restrict__ A, const float* __restrict__ W,
    const float* __restrict__ bias, float* __restrict__ C,
    int M, int N, int K)
{
    __shared__ unsigned As[2][16][136];
    __shared__ unsigned Bs[2][16][136];
    int tid = threadIdx.x;
    const float* Ab = A + (size_t)(blockIdx.y * 128) * K;
    const float* Wb = W + (size_t)(blockIdx.x * 128) * K;
    float acc[4][4][4] = {};
    mma_loop_128x128_db(Ab, K, Wb, K, K / 16, As, Bs, acc, tid);

    int warp = tid >> 5, lane = tid & 31;
    int wm = warp >> 2, wn = warp & 3;
    int grp = lane >> 2, qd = lane & 3;
    int row0 = blockIdx.y * 128 + wm * 64;
    int col0 = blockIdx.x * 128 + wn * 32;
    #pragma unroll
    for (int mi = 0; mi < 4; mi++) {
        #pragma unroll
        for (int ni = 0; ni < 4; ni++) {
            int r  = row0 + mi * 16 + grp;
            int cc = col0 + ni * 8 + qd * 2;
            float b0 = bias[cc], b1 = bias[cc + 1];
            *(float2*)(C + (size_t)r * N + cc) =
                make_float2(acc[mi][ni][0] + b0, acc[mi][ni][1] + b1);
            *(float2*)(C + (size_t)(r + 8) * N + cc) =
                make_float2(acc[mi][ni][2] + b0, acc[mi][ni][3] + b1);
        }
    }
}

// ---------------------------------------------------------------------------
// score[bh, sq, sk] = (1/8) * q . k
// ---------------------------------------------------------------------------
__global__ __launch_bounds__(256, 2) void attn_scores_tf32(float* __restrict__ score)
{
    __shared__ unsigned As[2][16][136];
    __shared__ unsigned Bs[2][16][136];
    int tid = threadIdx.x;
    int bh = blockIdx.z, b = bh >> 4, h = bh & 15;
    const float* qb = g_q + (size_t)b * SEQ * DIM + (size_t)(blockIdx.y * 128) * DIM + h * DK;
    const float* kb = g_k + (size_t)b * SEQ * DIM + (size_t)(blockIdx.x * 128) * DIM + h * DK;
    float acc[4][4][4] = {};
    mma_loop_128x128_db(qb, DIM, kb, DIM, DK / 16, As, Bs, acc, tid);

    int warp = tid >> 5, lane = tid & 31;
    int wm = warp >> 2, wn = warp & 3;
    int grp = lane >> 2, qd = lane & 3;
    const float alpha = 0.125f;
    float* ob = score + (size_t)bh * SEQ * SEQ;
    int row0 = blockIdx.y * 128 + wm * 64;
    int col0 = blockIdx.x * 128 + wn * 32;
    #pragma unroll
    for (int mi = 0; mi < 4; mi++) {
        #pragma unroll
        for (int ni = 0; ni < 4; ni++) {
            int r  = row0 + mi * 16 + grp;
            int cc = col0 + ni * 8 + qd * 2;
            *(float2*)(ob + (size_t)r * SEQ + cc) =
                make_float2(acc[mi][ni][0] * alpha, acc[mi][ni][1] * alpha);
            *(float2*)(ob + (size_t)(r + 8) * SEQ + cc) =
                make_float2(acc[mi][ni][2] * alpha, acc[mi][ni][3] * alpha);
        }
    }
}

// ---------------------------------------------------------------------------
// In-place row softmax over last dim (SEQ=2048). One block per row.
// Warp-shuffle reductions.
// ---------------------------------------------------------------------------
__global__ __launch_bounds__(256) void softmax_rows(float* __restrict__ score)
{
    size_t row = blockIdx.x;
    float* p = score + row * SEQ;
    int tid = threadIdx.x;
    int lane = tid & 31, warp = tid >> 5;
    __shared__ float red[8];

    float4 x0 = ((const float4*)p)[tid * 2];
    float4 x1 = ((const float4*)p)[tid * 2 + 1];

    float m = fmaxf(fmaxf(fmaxf(x0.x, x0.y), fmaxf(x0.z, x0.w)),
                    fmaxf(fmaxf(x1.x, x1.y), fmaxf(x1.z, x1.w)));
    #pragma unroll
    for (int o = 16; o > 0; o >>= 1)
        m = fmaxf(m, __shfl_xor_sync(0xffffffffu, m, o));
    if (lane == 0) red[warp] = m;
    __syncthreads();
    {
        float t = red[lane & 7];
        #pragma unroll
        for (int o = 4; o > 0; o >>= 1)
            t = fmaxf(t, __shfl_xor_sync(0xffffffffu, t, o));
        m = t;
    }

    float4 e0, e1;
    e0.x = __expf(x0.x - m); e0.y = __expf(x0.y - m);
    e0.z = __expf(x0.z - m); e0.w = __expf(x0.w - m);
    e1.x = __expf(x1.x - m); e1.y = __expf(x1.y - m);
    e1.z = __expf(x1.z - m); e1.w = __expf(x1.w - m);

    float s = (e0.x + e0.y + e0.z + e0.w) + (e1.x + e1.y + e1.z + e1.w);
    #pragma unroll
    for (int o = 16; o > 0; o >>= 1)
        s += __shfl_xor_sync(0xffffffffu, s, o);
    __syncthreads();           // reuse red[] safely
    if (lane == 0) red[warp] = s;
    __syncthreads();
    {
        float t = red[lane & 7];
        #pragma unroll
        for (int o = 4; o > 0; o >>= 1)
            t += __shfl_xor_sync(0xffffffffu, t, o);
        s = t;
    }
    float inv = 1.0f / s;

    e0.x *= inv; e0.y *= inv; e0.z *= inv; e0.w *= inv;
    e1.x *= inv; e1.y *= inv; e1.z *= inv; e1.w *= inv;
    ((float4*)p)[tid * 2]     = e0;
    ((float4*)p)[tid * 2 + 1] = e1;
}

// ---------------------------------------------------------------------------
// blended[b,sq,h*64+d] = sum_t p[bh,sq,t] * v[b,t,h*64+d]
// Tile 128x64, K=2048, double-buffered. Warps 4(M) x 2(N), warp tile 32x32.
// ---------------------------------------------------------------------------
__global__ __launch_bounds__(256, 2) void attn_pv_tf32(const float* __restrict__ score)
{
    __shared__ unsigned Ps[2][16][136];
    __shared__ unsigned Vs[2][16][72];
    int tid = threadIdx.x;
    int bh = blockIdx.y, b = bh >> 4, h = bh & 15;
    const float* pb = score + (size_t)bh * SEQ * SEQ + (size_t)(blockIdx.x * 128) * SEQ;
    const float* vb = g_v + (size_t)b * SEQ * DIM + h * DK;

    int warp = tid >> 5, lane = tid & 31;
    int wm = warp >> 1, wn = warp & 1;
    int grp = lane >> 2, qd = lane & 3;
    int vr = tid >> 4;           // 0..15 (k)
    int vc = (tid & 15) << 2;    // 0..60 (n)
    float acc[2][4][4] = {};

    float4 pp[2], pv;
    ldg_tile(pb, SEQ, tid, pp);
    pv = *(const float4*)(vb + (size_t)vr * DIM + vc);
    sts_tile(Ps[0], tid, pp);
    Vs[0][vr][vc+0] = f2tf(pv.x); Vs[0][vr][vc+1] = f2tf(pv.y);
    Vs[0][vr][vc+2] = f2tf(pv.z); Vs[0][vr][vc+3] = f2tf(pv.w);
    __syncthreads();

    for (int t = 0; t < SEQ / 16; t++) {
        int cur = t & 1;
        if (t + 1 < SEQ / 16) {
            ldg_tile(pb + (t + 1) * 16, SEQ, tid, pp);
            pv = *(const float4*)(vb + (size_t)((t + 1) * 16 + vr) * DIM + vc);
        }
        #pragma unroll
        for (int kk = 0; kk < 16; kk += 8) {
            unsigned a[2][4], bfr[4][2];
            #pragma unroll
            for (int mi = 0; mi < 2; mi++) {
                int m = wm * 32 + mi * 16;
                a[mi][0] = Ps[cur][kk + qd    ][m + grp    ];
                a[mi][1] = Ps[cur][kk + qd    ][m + grp + 8];
                a[mi][2] = Ps[cur][kk + qd + 4][m + grp    ];
                a[mi][3] = Ps[cur][kk + qd + 4][m + grp + 8];
            }
            #pragma unroll
            for (int ni = 0; ni < 4; ni++) {
                int n = wn * 32 + ni * 8;
                bfr[ni][0] = Vs[cur][kk + qd    ][n + grp];
                bfr[ni][1] = Vs[cur][kk + qd + 4][n + grp];
            }
            #pragma unroll
            for (int mi = 0; mi < 2; mi++)
                #pragma unroll
                for (int ni = 0; ni < 4; ni++)
                    mma_tf32(acc[mi][ni], a[mi][0], a[mi][1], a[mi][2], a[mi][3],
                             bfr[ni][0], bfr[ni][1]);
        }
        if (t + 1 < SEQ / 16) {
            sts_tile(Ps[cur ^ 1], tid, pp);
            Vs[cur^1][vr][vc+0] = f2tf(pv.x); Vs[cur^1][vr][vc+1] = f2tf(pv.y);
            Vs[cur^1][vr][vc+2] = f2tf(pv.z); Vs[cur^1][vr][vc+3] = f2tf(pv.w);
            __syncthreads();
        }
    }

    int row0 = blockIdx.x * 128 + wm * 32;
    int col0 = h * DK + wn * 32;
    float* ob = g_bl + (size_t)b * SEQ * DIM;
    #pragma unroll
    for (int mi = 0; mi < 2; mi++) {
        #pragma unroll
        for (int ni = 0; ni < 4; ni++) {
            int r  = row0 + mi * 16 + grp;
            int cc = col0 + ni * 8 + qd * 2;
            *(float2*)(ob + (size_t)r * DIM + cc) =
                make_float2(acc[mi][ni][0], acc[mi][ni][1]);
            *(float2*)(ob + (size_t)(r + 8) * DIM + cc) =
                make_float2(acc[mi][ni][2], acc[mi][ni][3]);
        }
    }
}

// ---------------------------------------------------------------------------
extern "C" void kernel_launch(void* const* d_in, const int* in_sizes, int n_in,
                              void* d_out, int out_size)
{
    const float* query = (const float*)d_in[0];
    const float* key   = (const float*)d_in[1];
    const float* value = (const float*)d_in[2];
    const float* Wq    = (const float*)d_in[3];
    const float* bq    = (const float*)d_in[4];
    const float* Wk    = (const float*)d_in[5];
    const float* bk    = (const float*)d_in[6];
    const float* Wv    = (const float*)d_in[7];
    const float* bv    = (const float*)d_in[8];
    const float* Wo    = (const float*)d_in[9];
    const float* bo    = (const float*)d_in[10];

    float* out   = (float*)d_out;                          // [B,S,D]
    float* score = out + (size_t)BSZ * SEQ * DIM;          // [B,H,S,S]

    float *pq, *pk, *pv, *pbl;
    cudaGetSymbolAddress((void**)&pq,  g_q);
    cudaGetSymbolAddress((void**)&pk,  g_k);
    cudaGetSymbolAddress((void**)&pv,  g_v);
    cudaGetSymbolAddress((void**)&pbl, g_bl);

    dim3 gp(DIM / 128, MTOT / 128);   // (8, 32)
    gemm_tf32_bias<<<gp, 256>>>(query, Wq, bq, pq, MTOT, DIM, DIM);
    gemm_tf32_bias<<<gp, 256>>>(key,   Wk, bk, pk, MTOT, DIM, DIM);
    gemm_tf32_bias<<<gp, 256>>>(value, Wv, bv, pv, MTOT, DIM, DIM);

    attn_scores_tf32<<<dim3(SEQ / 128, SEQ / 128, BH), 256>>>(score);
    softmax_rows<<<BH * SEQ, 256>>>(score);
    attn_pv_tf32<<<dim3(SEQ / 128, BH), 256>>>(score);

    gemm_tf32_bias<<<gp, 256>>>(pbl, Wo, bo, out, MTOT, DIM, DIM);
}

// round 4
// speedup vs baseline: 2.1141x; 1.0702x over previous
#include <cuda_runtime.h>
#include <math.h>

#define BSZ 2
#define SEQ 2048
#define DIM 1024
#define NH  16
#define DK  64
#define BH  (BSZ*NH)   // 32
#define MTOT (BSZ*SEQ) // 4096
#define NROWS (BH*SEQ) // 65536
#define NCT  16        // col tiles of 128 per row

// Scratch (allocation-free rule: __device__ globals)
__device__ float g_q [BSZ*SEQ*DIM];
__device__ float g_k [BSZ*SEQ*DIM];
__device__ float g_v [BSZ*SEQ*DIM];
__device__ float g_bl[BSZ*SEQ*DIM];
__device__ float g_smax  [NROWS*NCT];
__device__ float g_ssum  [NROWS*NCT];
__device__ float g_factor[NROWS*NCT];

// ---------------------------------------------------------------------------
// tf32 helpers
// ---------------------------------------------------------------------------
__device__ __forceinline__ unsigned f2tf(float x) {
    unsigned r;
    asm("cvt.rna.tf32.f32 %0, %1;" : "=r"(r) : "f"(x));
    return r;
}

__device__ __forceinline__ void mma_tf32(float c[4],
    unsigned a0, unsigned a1, unsigned a2, unsigned a3,
    unsigned b0, unsigned b1)
{
    asm volatile(
        "mma.sync.aligned.m16n8k8.row.col.f32.tf32.tf32.f32 "
        "{%0,%1,%2,%3}, {%4,%5,%6,%7}, {%8,%9}, {%0,%1,%2,%3};\n"
        : "+f"(c[0]), "+f"(c[1]), "+f"(c[2]), "+f"(c[3])
        : "r"(a0), "r"(a1), "r"(a2), "r"(a3), "r"(b0), "r"(b1));
}

// 128x16 tile global load, 128 threads, 4 float4 / thread
__device__ __forceinline__ void ldg4(
    const float* __restrict__ src, int lda, int tid, float4 v[4])
{
    #pragma unroll
    for (int i = 0; i < 4; i++) {
        int id = tid + i * 128;
        int r  = id >> 2;
        int c  = (id & 3) << 2;
        v[i] = *(const float4*)(src + (size_t)r * lda + c);
    }
}

__device__ __forceinline__ void sts4(
    unsigned (*dst)[136], int tid, const float4 v[4])
{
    #pragma unroll
    for (int i = 0; i < 4; i++) {
        int id = tid + i * 128;
        int r  = id >> 2;
        int c  = (id & 3) << 2;
        dst[c+0][r] = f2tf(v[i].x);
        dst[c+1][r] = f2tf(v[i].y);
        dst[c+2][r] = f2tf(v[i].z);
        dst[c+3][r] = f2tf(v[i].w);
    }
}

// Double-buffered 128x128 mainloop, 128 threads, warps 2x2, warp tile 64x64.
__device__ __forceinline__ void mma_loop(
    const float* __restrict__ A, int lda,
    const float* __restrict__ B, int ldb, int nk,
    unsigned (*As)[16][136], unsigned (*Bs)[16][136],
    float acc[4][8][4], int tid)
{
    int warp = tid >> 5, lane = tid & 31;
    int wm = warp >> 1, wn = warp & 1;
    int grp = lane >> 2, qd = lane & 3;

    float4 pa[4], pb[4];
    ldg4(A, lda, tid, pa);
    ldg4(B, ldb, tid, pb);
    sts4(As[0], tid, pa);
    sts4(Bs[0], tid, pb);
    __syncthreads();

    for (int t = 0; t < nk; t++) {
        int cur = t & 1;
        if (t + 1 < nk) {
            ldg4(A + (t + 1) * 16, lda, tid, pa);
            ldg4(B + (t + 1) * 16, ldb, tid, pb);
        }
        #pragma unroll
        for (int kk = 0; kk < 16; kk += 8) {
            unsigned a[4][4], bf[8][2];
            #pragma unroll
            for (int mi = 0; mi < 4; mi++) {
                int m = wm * 64 + mi * 16;
                a[mi][0] = As[cur][kk + qd    ][m + grp    ];
                a[mi][1] = As[cur][kk + qd    ][m + grp + 8];
                a[mi][2] = As[cur][kk + qd + 4][m + grp    ];
                a[mi][3] = As[cur][kk + qd + 4][m + grp + 8];
            }
            #pragma unroll
            for (int ni = 0; ni < 8; ni++) {
                int n = wn * 64 + ni * 8 + grp;
                bf[ni][0] = Bs[cur][kk + qd    ][n];
                bf[ni][1] = Bs[cur][kk + qd + 4][n];
            }
            #pragma unroll
            for (int mi = 0; mi < 4; mi++)
                #pragma unroll
                for (int ni = 0; ni < 8; ni++)
                    mma_tf32(acc[mi][ni], a[mi][0], a[mi][1], a[mi][2], a[mi][3],
                             bf[ni][0], bf[ni][1]);
        }
        if (t + 1 < nk) {
            sts4(As[cur ^ 1], tid, pa);
            sts4(Bs[cur ^ 1], tid, pb);
            __syncthreads();
        }
    }
}

// ---------------------------------------------------------------------------
// C[M,N] = A[M,K] @ W[N,K]^T + bias[N]
// ---------------------------------------------------------------------------
__global__ __launch_bounds__(128, 2) void gemm_tf32_bias(
    const float* __restrict__ A, const float* __restrict__ W,
    const float* __restrict__ bias, float* __restrict__ C,
    int M, int N, int K)
{
    __shared__ unsigned As[2][16][136];
    __shared__ unsigned Bs[2][16][136];
    int tid = threadIdx.x;
    const float* Ab = A + (size_t)(blockIdx.y * 128) * K;
    const float* Wb = W + (size_t)(blockIdx.x * 128) * K;
    float acc[4][8][4] = {};
    mma_loop(Ab, K, Wb, K, K / 16, As, Bs, acc, tid);

    int warp = tid >> 5, lane = tid & 31;
    int wm = warp >> 1, wn = warp & 1;
    int grp = lane >> 2, qd = lane & 3;
    int row0 = blockIdx.y * 128 + wm * 64;
    int col0 = blockIdx.x * 128 + wn * 64;
    #pragma unroll
    for (int mi = 0; mi < 4; mi++) {
        #pragma unroll
        for (int ni = 0; ni < 8; ni++) {
            int r  = row0 + mi * 16 + grp;
            int cc = col0 + ni * 8 + qd * 2;
            float b0 = bias[cc], b1 = bias[cc + 1];
            *(float2*)(C + (size_t)r * N + cc) =
                make_float2(acc[mi][ni][0] + b0, acc[mi][ni][1] + b1);
            *(float2*)(C + (size_t)(r + 8) * N + cc) =
                make_float2(acc[mi][ni][2] + b0, acc[mi][ni][3] + b1);
        }
    }
}

// ---------------------------------------------------------------------------
// scores + partial softmax: writes e = exp(x*alpha - m_tile) and per-row-tile
// (max, sumexp) partials.
// grid (16 key tiles, 16 query tiles, 32 bh)
// ---------------------------------------------------------------------------
__global__ __launch_bounds__(128, 2) void attn_scores_stats(float* __restrict__ score)
{
    __shared__ unsigned As[2][16][136];
    __shared__ unsigned Bs[2][16][136];
    __shared__ float rstat[128][2];
    int tid = threadIdx.x;
    int bh = blockIdx.z, b = bh >> 4, h = bh & 15;
    const float* qb = g_q + (size_t)b * SEQ * DIM + (size_t)(blockIdx.y * 128) * DIM + h * DK;
    const float* kb = g_k + (size_t)b * SEQ * DIM + (size_t)(blockIdx.x * 128) * DIM + h * DK;
    float acc[4][8][4] = {};
    mma_loop(qb, DIM, kb, DIM, DK / 16, As, Bs, acc, tid);

    int warp = tid >> 5, lane = tid & 31;
    int wm = warp >> 1, wn = warp & 1;
    int grp = lane >> 2, qd = lane & 3;
    const float alpha = 0.125f;

    // scale in place
    #pragma unroll
    for (int mi = 0; mi < 4; mi++)
        #pragma unroll
        for (int ni = 0; ni < 8; ni++)
            #pragma unroll
            for (int j = 0; j < 4; j++)
                acc[mi][ni][j] *= alpha;

    // row max (per mi: rows r and r+8)
    float msel[4][2];
    #pragma unroll
    for (int mi = 0; mi < 4; mi++) {
        float mA = -1e30f, mB = -1e30f;
        #pragma unroll
        for (int ni = 0; ni < 8; ni++) {
            mA = fmaxf(mA, fmaxf(acc[mi][ni][0], acc[mi][ni][1]));
            mB = fmaxf(mB, fmaxf(acc[mi][ni][2], acc[mi][ni][3]));
        }
        mA = fmaxf(mA, __shfl_xor_sync(0xffffffffu, mA, 1));
        mA = fmaxf(mA, __shfl_xor_sync(0xffffffffu, mA, 2));
        mB = fmaxf(mB, __shfl_xor_sync(0xffffffffu, mB, 1));
        mB = fmaxf(mB, __shfl_xor_sync(0xffffffffu, mB, 2));
        int rA = wm * 64 + mi * 16 + grp;
        if (qd == 0) { rstat[rA][wn] = mA; rstat[rA + 8][wn] = mB; }
    }
    __syncthreads();
    #pragma unroll
    for (int mi = 0; mi < 4; mi++) {
        int rA = wm * 64 + mi * 16 + grp;
        msel[mi][0] = fmaxf(rstat[rA][0],     rstat[rA][1]);
        msel[mi][1] = fmaxf(rstat[rA + 8][0], rstat[rA + 8][1]);
    }
    __syncthreads();

    // exp in place + row sums
    float ssel[4][2];
    #pragma unroll
    for (int mi = 0; mi < 4; mi++) {
        float sA = 0.f, sB = 0.f;
        #pragma unroll
        for (int ni = 0; ni < 8; ni++) {
            acc[mi][ni][0] = __expf(acc[mi][ni][0] - msel[mi][0]);
            acc[mi][ni][1] = __expf(acc[mi][ni][1] - msel[mi][0]);
            acc[mi][ni][2] = __expf(acc[mi][ni][2] - msel[mi][1]);
            acc[mi][ni][3] = __expf(acc[mi][ni][3] - msel[mi][1]);
            sA += acc[mi][ni][0] + acc[mi][ni][1];
            sB += acc[mi][ni][2] + acc[mi][ni][3];
        }
        sA += __shfl_xor_sync(0xffffffffu, sA, 1);
        sA += __shfl_xor_sync(0xffffffffu, sA, 2);
        sB += __shfl_xor_sync(0xffffffffu, sB, 1);
        sB += __shfl_xor_sync(0xffffffffu, sB, 2);
        int rA = wm * 64 + mi * 16 + grp;
        if (qd == 0) { rstat[rA][wn] = sA; rstat[rA + 8][wn] = sB; }
    }
    __syncthreads();
    #pragma unroll
    for (int mi = 0; mi < 4; mi++) {
        int rA = wm * 64 + mi * 16 + grp;
        ssel[mi][0] = rstat[rA][0]     + rstat[rA][1];
        ssel[mi][1] = rstat[rA + 8][0] + rstat[rA + 8][1];
    }

    // write e tile
    float* ob = score + (size_t)bh * SEQ * SEQ;
    int row0 = blockIdx.y * 128 + wm * 64;
    int col0 = blockIdx.x * 128 + wn * 64;
    #pragma unroll
    for (int mi = 0; mi < 4; mi++) {
        #pragma unroll
        for (int ni = 0; ni < 8; ni++) {
            int r  = row0 + mi * 16 + grp;
            int cc = col0 + ni * 8 + qd * 2;
            *(float2*)(ob + (size_t)r * SEQ + cc) =
                make_float2(acc[mi][ni][0], acc[mi][ni][1]);
            *(float2*)(ob + (size_t)(r + 8) * SEQ + cc) =
                make_float2(acc[mi][ni][2], acc[mi][ni][3]);
        }
    }

    // write stats
    if (wn == 0 && qd == 0) {
        #pragma unroll
        for (int mi = 0; mi < 4; mi++) {
            #pragma unroll
            for (int half = 0; half < 2; half++) {
                int rowg = blockIdx.y * 128 + wm * 64 + mi * 16 + half * 8 + grp;
                size_t idx = ((size_t)(bh << 11) + rowg) * NCT + blockIdx.x;
                g_smax[idx] = msel[mi][half];
                g_ssum[idx] = ssel[mi][half];
            }
        }
    }
}

// ---------------------------------------------------------------------------
// combine partials: factor_i = exp(m_i - m) / sum
// ---------------------------------------------------------------------------
__global__ __launch_bounds__(256) void combine_stats()
{
    int gid = blockIdx.x * 256 + threadIdx.x;   // one row per thread
    const float* mx = g_smax + (size_t)gid * NCT;
    const float* sm = g_ssum + (size_t)gid * NCT;
    float mv[NCT];
    float m = -1e30f;
    #pragma unroll
    for (int i = 0; i < NCT; i++) { mv[i] = mx[i]; m = fmaxf(m, mv[i]); }
    float s = 0.f;
    float ev[NCT];
    #pragma unroll
    for (int i = 0; i < NCT; i++) { ev[i] = __expf(mv[i] - m); s += sm[i] * ev[i]; }
    float inv = 1.0f / s;
    #pragma unroll
    for (int i = 0; i < NCT; i++) g_factor[(size_t)gid * NCT + i] = ev[i] * inv;
}

// ---------------------------------------------------------------------------
// PV fused: reads e, p = e * factor[row][ct], writes p in place (final probs),
// accumulates blended = P @ V into g_bl.
// 128 threads, tile 128x64, warps 2x2, warp tile 64x32.
// ---------------------------------------------------------------------------
__global__ __launch_bounds__(128, 2) void attn_pv_fused(float* __restrict__ score)
{
    __shared__ unsigned Ps[2][16][136];
    __shared__ unsigned Vs[2][16][72];
    int tid = threadIdx.x;
    int bh = blockIdx.y, b = bh >> 4, h = bh & 15;
    int row0 = blockIdx.x * 128;
    float* pb = score + (size_t)bh * SEQ * SEQ + (size_t)row0 * SEQ;
    const float* vb = g_v + (size_t)b * SEQ * DIM + h * DK;
    const float* fb = g_factor + ((size_t)(bh << 11) + row0) * NCT;

    int warp = tid >> 5, lane = tid & 31;
    int wm = warp >> 1, wn = warp & 1;
    int grp = lane >> 2, qd = lane & 3;
    int vr = (tid) >> 4;          // plus i*128 below
    float acc[4][4][4] = {};

    float4 pe[4]; float pf[4]; float4 pvv[2];

    // prologue: tile 0
    #pragma unroll
    for (int i = 0; i < 4; i++) {
        int id = tid + i * 128;
        int r  = id >> 2;
        int c  = (id & 3) << 2;
        pe[i] = *(const float4*)(pb + (size_t)r * SEQ + c);
        pf[i] = fb[r * NCT + 0];
    }
    #pragma unroll
    for (int i = 0; i < 2; i++) {
        int id = tid + i * 128;
        int r = id >> 4, c = (id & 15) << 2;
        pvv[i] = *(const float4*)(vb + (size_t)r * DIM + c);
    }
    #pragma unroll
    for (int i = 0; i < 4; i++) {
        int id = tid + i * 128;
        int r  = id >> 2;
        int c  = (id & 3) << 2;
        float4 p = make_float4(pe[i].x * pf[i], pe[i].y * pf[i],
                               pe[i].z * pf[i], pe[i].w * pf[i]);
        *(float4*)(pb + (size_t)r * SEQ + c) = p;
        Ps[0][c+0][r] = f2tf(p.x); Ps[0][c+1][r] = f2tf(p.y);
        Ps[0][c+2][r] = f2tf(p.z); Ps[0][c+3][r] = f2tf(p.w);
    }
    #pragma unroll
    for (int i = 0; i < 2; i++) {
        int id = tid + i * 128;
        int r = id >> 4, c = (id & 15) << 2;
        Vs[0][r][c+0] = f2tf(pvv[i].x); Vs[0][r][c+1] = f2tf(pvv[i].y);
        Vs[0][r][c+2] = f2tf(pvv[i].z); Vs[0][r][c+3] = f2tf(pvv[i].w);
    }
    __syncthreads();

    const int NK = SEQ / 16;   // 128
    for (int t = 0; t < NK; t++) {
        int cur = t & 1;
        if (t + 1 < NK) {
            int ct = (t + 1) >> 3;
            #pragma unroll
            for (int i = 0; i < 4; i++) {
                int id = tid + i * 128;
                int r  = id >> 2;
                int c  = (id & 3) << 2;
                pe[i] = *(const float4*)(pb + (size_t)r * SEQ + (t + 1) * 16 + c);
                pf[i] = fb[r * NCT + ct];
            }
            #pragma unroll
            for (int i = 0; i < 2; i++) {
                int id = tid + i * 128;
                int r = id >> 4, c = (id & 15) << 2;
                pvv[i] = *(const float4*)(vb + (size_t)((t + 1) * 16 + r) * DIM + c);
            }
        }
        #pragma unroll
        for (int kk = 0; kk < 16; kk += 8) {
            unsigned a[4][4], bf[4][2];
            #pragma unroll
            for (int mi = 0; mi < 4; mi++) {
                int m = wm * 64 + mi * 16;
                a[mi][0] = Ps[cur][kk + qd    ][m + grp    ];
                a[mi][1] = Ps[cur][kk + qd    ][m + grp + 8];
                a[mi][2] = Ps[cur][kk + qd + 4][m + grp    ];
                a[mi][3] = Ps[cur][kk + qd + 4][m + grp + 8];
            }
            #pragma unroll
            for (int ni = 0; ni < 4; ni++) {
                int n = wn * 32 + ni * 8 + grp;
                bf[ni][0] = Vs[cur][kk + qd    ][n];
                bf[ni][1] = Vs[cur][kk + qd + 4][n];
            }
            #pragma unroll
            for (int mi = 0; mi < 4; mi++)
                #pragma unroll
                for (int ni = 0; ni < 4; ni++)
                    mma_tf32(acc[mi][ni], a[mi][0], a[mi][1], a[mi][2], a[mi][3],
                             bf[ni][0], bf[ni][1]);
        }
        if (t + 1 < NK) {
            int nxt = cur ^ 1;
            #pragma unroll
            for (int i = 0; i < 4; i++) {
                int id = tid + i * 128;
                int r  = id >> 2;
                int c  = (id & 3) << 2;
                float4 p = make_float4(pe[i].x * pf[i], pe[i].y * pf[i],
                                       pe[i].z * pf[i], pe[i].w * pf[i]);
                *(float4*)(pb + (size_t)r * SEQ + (t + 1) * 16 + c) = p;
                Ps[nxt][c+0][r] = f2tf(p.x); Ps[nxt][c+1][r] = f2tf(p.y);
                Ps[nxt][c+2][r] = f2tf(p.z); Ps[nxt][c+3][r] = f2tf(p.w);
            }
            #pragma unroll
            for (int i = 0; i < 2; i++) {
                int id = tid + i * 128;
                int r = id >> 4, c = (id & 15) << 2;
                Vs[nxt][r][c+0] = f2tf(pvv[i].x); Vs[nxt][r][c+1] = f2tf(pvv[i].y);
                Vs[nxt][r][c+2] = f2tf(pvv[i].z); Vs[nxt][r][c+3] = f2tf(pvv[i].w);
            }
            __syncthreads();
        }
    }

    float* ob = g_bl + (size_t)b * SEQ * DIM;
    int r0 = row0 + wm * 64;
    int c0 = h * DK + wn * 32;
    #pragma unroll
    for (int mi = 0; mi < 4; mi++) {
        #pragma unroll
        for (int ni = 0; ni < 4; ni++) {
            int r  = r0 + mi * 16 + grp;
            int cc = c0 + ni * 8 + qd * 2;
            *(float2*)(ob + (size_t)r * DIM + cc) =
                make_float2(acc[mi][ni][0], acc[mi][ni][1]);
            *(float2*)(ob + (size_t)(r + 8) * DIM + cc) =
                make_float2(acc[mi][ni][2], acc[mi][ni][3]);
        }
    }
}

// ---------------------------------------------------------------------------
extern "C" void kernel_launch(void* const* d_in, const int* in_sizes, int n_in,
                              void* d_out, int out_size)
{
    const float* query = (const float*)d_in[0];
    const float* key   = (const float*)d_in[1];
    const float* value = (const float*)d_in[2];
    const float* Wq    = (const float*)d_in[3];
    const float* bq    = (const float*)d_in[4];
    const float* Wk    = (const float*)d_in[5];
    const float* bk    = (const float*)d_in[6];
    const float* Wv    = (const float*)d_in[7];
    const float* bv    = (const float*)d_in[8];
    const float* Wo    = (const float*)d_in[9];
    const float* bo    = (const float*)d_in[10];

    float* out   = (float*)d_out;                          // [B,S,D]
    float* score = out + (size_t)BSZ * SEQ * DIM;          // [B,H,S,S]

    float *pq, *pk, *pv, *pbl;
    cudaGetSymbolAddress((void**)&pq,  g_q);
    cudaGetSymbolAddress((void**)&pk,  g_k);
    cudaGetSymbolAddress((void**)&pv,  g_v);
    cudaGetSymbolAddress((void**)&pbl, g_bl);

    dim3 gp(DIM / 128, MTOT / 128);   // (8, 32)
    gemm_tf32_bias<<<gp, 128>>>(query, Wq, bq, pq, MTOT, DIM, DIM);
    gemm_tf32_bias<<<gp, 128>>>(key,   Wk, bk, pk, MTOT, DIM, DIM);
    gemm_tf32_bias<<<gp, 128>>>(value, Wv, bv, pv, MTOT, DIM, DIM);

    attn_scores_stats<<<dim3(SEQ / 128, SEQ / 128, BH), 128>>>(score);
    combine_stats<<<NROWS / 256, 256>>>();
    attn_pv_fused<<<dim3(SEQ / 128, BH), 128>>>(score);

    gemm_tf32_bias<<<gp, 128>>>(pbl, Wo, bo, out, MTOT, DIM, DIM);
}

// round 7
// speedup vs baseline: 2.1849x; 1.0335x over previous
#include <cuda_runtime.h>
#include <math.h>
#include <stdint.h>

#define BSZ 2
#define SEQ 2048
#define DIM 1024
#define NH  16
#define DK  64
#define BH  (BSZ*NH)   // 32
#define MTOT (BSZ*SEQ) // 4096
#define NROWS (BH*SEQ) // 65536
#define NCT  16        // col tiles of 128 per row

// Scratch (allocation-free rule: __device__ globals)
__device__ float g_q [BSZ*SEQ*DIM];
__device__ float g_k [BSZ*SEQ*DIM];
__device__ float g_v [BSZ*SEQ*DIM];
__device__ float g_bl[BSZ*SEQ*DIM];
__device__ float g_smax  [NROWS*NCT];
__device__ float g_ssum  [NROWS*NCT];
__device__ float g_factor[NROWS*NCT];

// ---------------------------------------------------------------------------
// helpers
// ---------------------------------------------------------------------------
__device__ __forceinline__ unsigned f2tf(float x) {
    unsigned r;
    asm("cvt.rna.tf32.f32 %0, %1;" : "=r"(r) : "f"(x));
    return r;
}

__device__ __forceinline__ void mma_tf32(float c[4],
    unsigned a0, unsigned a1, unsigned a2, unsigned a3,
    unsigned b0, unsigned b1)
{
    asm volatile(
        "mma.sync.aligned.m16n8k8.row.col.f32.tf32.tf32.f32 "
        "{%0,%1,%2,%3}, {%4,%5,%6,%7}, {%8,%9}, {%0,%1,%2,%3};\n"
        : "+f"(c[0]), "+f"(c[1]), "+f"(c[2]), "+f"(c[3])
        : "r"(a0), "r"(a1), "r"(a2), "r"(a3), "r"(b0), "r"(b1));
}

__device__ __forceinline__ unsigned smem_u32(const void* p) {
    unsigned a;
    asm("{ .reg .u64 t; cvta.to.shared.u64 t, %1; cvt.u32.u64 %0, t; }"
        : "=r"(a) : "l"(p));
    return a;
}

#define CPA_COMMIT() asm volatile("cp.async.commit_group;" ::: "memory")
#define CPA_WAIT1()  asm volatile("cp.async.wait_group 1;" ::: "memory")
#define CPA_WAIT0()  asm volatile("cp.async.wait_group 0;" ::: "memory")

#define TPAD 20   // floats per padded row (80B; conflict-free fragment LDS)

// cp.async one 128x16 f32 tile into padded smem [128][TPAD]; 256 threads.
__device__ __forceinline__ void cpa_tile(
    float (*dst)[TPAD], const float* __restrict__ src, int lda, int tid)
{
    #pragma unroll
    for (int i = 0; i < 2; i++) {
        int id = tid + i * 256;       // 0..511
        int r  = id >> 2;             // 0..127
        int c4 = (id & 3) << 2;       // 0,4,8,12
        unsigned sa = smem_u32(&dst[r][c4]);
        asm volatile("cp.async.cg.shared.global [%0], [%1], 16;"
                     :: "r"(sa), "l"(src + (size_t)r * lda + c4) : "memory");
    }
}

// One 16-K tile of MMAs. Warp grid 2(M)x4(N), warp tile 64x32.
__device__ __forceinline__ void tile_mma(
    const float (*As)[TPAD], const float (*Bs)[TPAD],
    float acc[4][4][4], int wm, int wn, int grp, int qd)
{
    #pragma unroll
    for (int kk = 0; kk < 16; kk += 8) {
        unsigned a[4][4], b[4][2];
        #pragma unroll
        for (int mi = 0; mi < 4; mi++) {
            int m = wm * 64 + mi * 16;
            a[mi][0] = f2tf(As[m + grp    ][kk + qd    ]);
            a[mi][1] = f2tf(As[m + grp + 8][kk + qd    ]);
            a[mi][2] = f2tf(As[m + grp    ][kk + qd + 4]);
            a[mi][3] = f2tf(As[m + grp + 8][kk + qd + 4]);
        }
        #pragma unroll
        for (int ni = 0; ni < 4; ni++) {
            int n = wn * 32 + ni * 8 + grp;
            b[ni][0] = f2tf(Bs[n][kk + qd    ]);
            b[ni][1] = f2tf(Bs[n][kk + qd + 4]);
        }
        #pragma unroll
        for (int mi = 0; mi < 4; mi++)
            #pragma unroll
            for (int ni = 0; ni < 4; ni++)
                mma_tf32(acc[mi][ni], a[mi][0], a[mi][1], a[mi][2], a[mi][3],
                         b[ni][0], b[ni][1]);
    }
}

// 3-stage cp.async mainloop over nk 16-K tiles (nk >= 3).
__device__ __forceinline__ void cpa_loop(
    const float* __restrict__ A, int lda,
    const float* __restrict__ B, int ldb, int nk,
    float (*As)[128][TPAD], float (*Bs)[128][TPAD],
    float acc[4][4][4], int tid, int wm, int wn, int grp, int qd)
{
    cpa_tile(As[0], A, lda, tid);
    cpa_tile(Bs[0], B, ldb, tid);
    CPA_COMMIT();
    cpa_tile(As[1], A + 16, lda, tid);
    cpa_tile(Bs[1], B + 16, ldb, tid);
    CPA_COMMIT();

    int cur = 0;
    for (int t = 0; t < nk; t++) {
        if (t < nk - 1) CPA_WAIT1(); else CPA_WAIT0();
        __syncthreads();
        tile_mma(As[cur], Bs[cur], acc, wm, wn, grp, qd);
        if (t + 2 < nk) {
            int nxt = cur + 2; if (nxt >= 3) nxt -= 3;
            cpa_tile(As[nxt], A + (t + 2) * 16, lda, tid);
            cpa_tile(Bs[nxt], B + (t + 2) * 16, ldb, tid);
            CPA_COMMIT();
        }
        // barrier at top of next iter protects reuse of freed buffer
        if (++cur == 3) cur = 0;
    }
}

#define GEMM_SMEM (3 * 128 * TPAD * 4 * 2)          // 61440
#define SC_SMEM   (GEMM_SMEM + 128 * 4 * 4)         // + rstat

// ---------------------------------------------------------------------------
// GEMM: C[M,N] = A[M,K] @ W[N,K]^T + bias[N]; CTA 128x128, 256 thr.
// ---------------------------------------------------------------------------
__global__ __launch_bounds__(256, 2) void gemm_cpa(
    const float* __restrict__ A, const float* __restrict__ W,
    const float* __restrict__ bias, float* __restrict__ C,
    int M, int N, int K)
{
    extern __shared__ float sm[];
    float (*As)[128][TPAD] = (float (*)[128][TPAD])sm;
    float (*Bs)[128][TPAD] = (float (*)[128][TPAD])(sm + 3 * 128 * TPAD);

    int tid = threadIdx.x;
    int warp = tid >> 5, lane = tid & 31;
    int wm = warp >> 2, wn = warp & 3;
    int grp = lane >> 2, qd = lane & 3;

    const float* Ab = A + (size_t)(blockIdx.y * 128) * K;
    const float* Wb = W + (size_t)(blockIdx.x * 128) * K;
    float acc[4][4][4] = {};
    cpa_loop(Ab, K, Wb, K, K / 16, As, Bs, acc, tid, wm, wn, grp, qd);

    int row0 = blockIdx.y * 128 + wm * 64;
    int col0 = blockIdx.x * 128 + wn * 32;
    #pragma unroll
    for (int mi = 0; mi < 4; mi++) {
        #pragma unroll
        for (int ni = 0; ni < 4; ni++) {
            int r  = row0 + mi * 16 + grp;
            int cc = col0 + ni * 8 + qd * 2;
            float b0 = bias[cc], b1 = bias[cc + 1];
            *(float2*)(C + (size_t)r * N + cc) =
                make_float2(acc[mi][ni][0] + b0, acc[mi][ni][1] + b1);
            *(float2*)(C + (size_t)(r + 8) * N + cc) =
                make_float2(acc[mi][ni][2] + b0, acc[mi][ni][3] + b1);
        }
    }
}

// ---------------------------------------------------------------------------
// scores + partial softmax: e = exp(x/8 - m_tile), per-row-tile (max,sum).
// ---------------------------------------------------------------------------
__global__ __launch_bounds__(256, 2) void attn_scores_stats(float* __restrict__ score)
{
    extern __shared__ float sm[];
    float (*As)[128][TPAD] = (float (*)[128][TPAD])sm;
    float (*Bs)[128][TPAD] = (float (*)[128][TPAD])(sm + 3 * 128 * TPAD);
    float (*rstat)[4]      = (float (*)[4])(sm + 6 * 128 * TPAD);

    int tid = threadIdx.x;
    int warp = tid >> 5, lane = tid & 31;
    int wm = warp >> 2, wn = warp & 3;
    int grp = lane >> 2, qd = lane & 3;
    int bh = blockIdx.z, b = bh >> 4, h = bh & 15;

    const float* qb = g_q + (size_t)b * SEQ * DIM + (size_t)(blockIdx.y * 128) * DIM + h * DK;
    const float* kb = g_k + (size_t)b * SEQ * DIM + (size_t)(blockIdx.x * 128) * DIM + h * DK;
    float acc[4][4][4] = {};
    cpa_loop(qb, DIM, kb, DIM, DK / 16, As, Bs, acc, tid, wm, wn, grp, qd);

    const float alpha = 0.125f;
    #pragma unroll
    for (int mi = 0; mi < 4; mi++)
        #pragma unroll
        for (int ni = 0; ni < 4; ni++)
            #pragma unroll
            for (int j = 0; j < 4; j++)
                acc[mi][ni][j] *= alpha;

    __syncthreads();   // tiles done; reuse smem region for stats only (rstat separate)

    // row max across this warp's 32 cols, then across 4 wn
    float msel[4][2];
    #pragma unroll
    for (int mi = 0; mi < 4; mi++) {
        float mA = -1e30f, mB = -1e30f;
        #pragma unroll
        for (int ni = 0; ni < 4; ni++) {
            mA = fmaxf(mA, fmaxf(acc[mi][ni][0], acc[mi][ni][1]));
            mB = fmaxf(mB, fmaxf(acc[mi][ni][2], acc[mi][ni][3]));
        }
        mA = fmaxf(mA, __shfl_xor_sync(0xffffffffu, mA, 1));
        mA = fmaxf(mA, __shfl_xor_sync(0xffffffffu, mA, 2));
        mB = fmaxf(mB, __shfl_xor_sync(0xffffffffu, mB, 1));
        mB = fmaxf(mB, __shfl_xor_sync(0xffffffffu, mB, 2));
        int rA = wm * 64 + mi * 16 + grp;
        if (qd == 0) { rstat[rA][wn] = mA; rstat[rA + 8][wn] = mB; }
    }
    __syncthreads();
    #pragma unroll
    for (int mi = 0; mi < 4; mi++) {
        int rA = wm * 64 + mi * 16 + grp;
        msel[mi][0] = fmaxf(fmaxf(rstat[rA][0],     rstat[rA][1]),
                            fmaxf(rstat[rA][2],     rstat[rA][3]));
        msel[mi][1] = fmaxf(fmaxf(rstat[rA + 8][0], rstat[rA + 8][1]),
                            fmaxf(rstat[rA + 8][2], rstat[rA + 8][3]));
    }
    __syncthreads();

    float ssel[4][2];
    #pragma unroll
    for (int mi = 0; mi < 4; mi++) {
        float sA = 0.f, sB = 0.f;
        #pragma unroll
        for (int ni = 0; ni < 4; ni++) {
            acc[mi][ni][0] = __expf(acc[mi][ni][0] - msel[mi][0]);
            acc[mi][ni][1] = __expf(acc[mi][ni][1] - msel[mi][0]);
            acc[mi][ni][2] = __expf(acc[mi][ni][2] - msel[mi][1]);
            acc[mi][ni][3] = __expf(acc[mi][ni][3] - msel[mi][1]);
            sA += acc[mi][ni][0] + acc[mi][ni][1];
            sB += acc[mi][ni][2] + acc[mi][ni][3];
        }
        sA += __shfl_xor_sync(0xffffffffu, sA, 1);
        sA += __shfl_xor_sync(0xffffffffu, sA, 2);
        sB += __shfl_xor_sync(0xffffffffu, sB, 1);
        sB += __shfl_xor_sync(0xffffffffu, sB, 2);
        int rA = wm * 64 + mi * 16 + grp;
        if (qd == 0) { rstat[rA][wn] = sA; rstat[rA + 8][wn] = sB; }
    }
    __syncthreads();
    #pragma unroll
    for (int mi = 0; mi < 4; mi++) {
        int rA = wm * 64 + mi * 16 + grp;
        ssel[mi][0] = (rstat[rA][0]     + rstat[rA][1])
                    + (rstat[rA][2]     + rstat[rA][3]);
        ssel[mi][1] = (rstat[rA + 8][0] + rstat[rA + 8][1])
                    + (rstat[rA + 8][2] + rstat[rA + 8][3]);
    }

    float* ob = score + (size_t)bh * SEQ * SEQ;
    int row0 = blockIdx.y * 128 + wm * 64;
    int col0 = blockIdx.x * 128 + wn * 32;
    #pragma unroll
    for (int mi = 0; mi < 4; mi++) {
        #pragma unroll
        for (int ni = 0; ni < 4; ni++) {
            int r  = row0 + mi * 16 + grp;
            int cc = col0 + ni * 8 + qd * 2;
            *(float2*)(ob + (size_t)r * SEQ + cc) =
                make_float2(acc[mi][ni][0], acc[mi][ni][1]);
            *(float2*)(ob + (size_t)(r + 8) * SEQ + cc) =
                make_float2(acc[mi][ni][2], acc[mi][ni][3]);
        }
    }

    if (wn == 0 && qd == 0) {
        #pragma unroll
        for (int mi = 0; mi < 4; mi++) {
            #pragma unroll
            for (int half = 0; half < 2; half++) {
                int rowg = blockIdx.y * 128 + wm * 64 + mi * 16 + half * 8 + grp;
                size_t idx = ((size_t)(bh << 11) + rowg) * NCT + blockIdx.x;
                g_smax[idx] = msel[mi][half];
                g_ssum[idx] = ssel[mi][half];
            }
        }
    }
}

// ---------------------------------------------------------------------------
__global__ __launch_bounds__(256) void combine_stats()
{
    int gid = blockIdx.x * 256 + threadIdx.x;
    const float* mx = g_smax + (size_t)gid * NCT;
    const float* smv = g_ssum + (size_t)gid * NCT;
    float mv[NCT];
    float m = -1e30f;
    #pragma unroll
    for (int i = 0; i < NCT; i++) { mv[i] = mx[i]; m = fmaxf(m, mv[i]); }
    float s = 0.f;
    float ev[NCT];
    #pragma unroll
    for (int i = 0; i < NCT; i++) { ev[i] = __expf(mv[i] - m); s += smv[i] * ev[i]; }
    float inv = 1.0f / s;
    #pragma unroll
    for (int i = 0; i < NCT; i++) g_factor[(size_t)gid * NCT + i] = ev[i] * inv;
}

// ---------------------------------------------------------------------------
// PV fused (unchanged from R4 passing version): p = e*factor written in place,
// blended += P @ V. 128 threads, warps 2x2, warp tile 64x32.
// ---------------------------------------------------------------------------
__global__ __launch_bounds__(128, 2) void attn_pv_fused(float* __restrict__ score)
{
    __shared__ unsigned Ps[2][16][136];
    __shared__ unsigned Vs[2][16][72];
    int tid = threadIdx.x;
    int bh = blockIdx.y, b = bh >> 4, h = bh & 15;
    int row0 = blockIdx.x * 128;
    float* pb = score + (size_t)bh * SEQ * SEQ + (size_t)row0 * SEQ;
    const float* vb = g_v + (size_t)b * SEQ * DIM + h * DK;
    const float* fb = g_factor + ((size_t)(bh << 11) + row0) * NCT;

    int warp = tid >> 5, lane = tid & 31;
    int wm = warp >> 1, wn = warp & 1;
    int grp = lane >> 2, qd = lane & 3;
    float acc[4][4][4] = {};

    float4 pe[4]; float pf[4]; float4 pvv[2];

    #pragma unroll
    for (int i = 0; i < 4; i++) {
        int id = tid + i * 128;
        int r  = id >> 2;
        int c  = (id & 3) << 2;
        pe[i] = *(const float4*)(pb + (size_t)r * SEQ + c);
        pf[i] = fb[r * NCT + 0];
    }
    #pragma unroll
    for (int i = 0; i < 2; i++) {
        int id = tid + i * 128;
        int r = id >> 4, c = (id & 15) << 2;
        pvv[i] = *(const float4*)(vb + (size_t)r * DIM + c);
    }
    #pragma unroll
    for (int i = 0; i < 4; i++) {
        int id = tid + i * 128;
        int r  = id >> 2;
        int c  = (id & 3) << 2;
        float4 p = make_float4(pe[i].x * pf[i], pe[i].y * pf[i],
                               pe[i].z * pf[i], pe[i].w * pf[i]);
        *(float4*)(pb + (size_t)r * SEQ + c) = p;
        Ps[0][c+0][r] = f2tf(p.x); Ps[0][c+1][r] = f2tf(p.y);
        Ps[0][c+2][r] = f2tf(p.z); Ps[0][c+3][r] = f2tf(p.w);
    }
    #pragma unroll
    for (int i = 0; i < 2; i++) {
        int id = tid + i * 128;
        int r = id >> 4, c = (id & 15) << 2;
        Vs[0][r][c+0] = f2tf(pvv[i].x); Vs[0][r][c+1] = f2tf(pvv[i].y);
        Vs[0][r][c+2] = f2tf(pvv[i].z); Vs[0][r][c+3] = f2tf(pvv[i].w);
    }
    __syncthreads();

    const int NK = SEQ / 16;
    for (int t = 0; t < NK; t++) {
        int cur = t & 1;
        if (t + 1 < NK) {
            int ct = (t + 1) >> 3;
            #pragma unroll
            for (int i = 0; i < 4; i++) {
                int id = tid + i * 128;
                int r  = id >> 2;
                int c  = (id & 3) << 2;
                pe[i] = *(const float4*)(pb + (size_t)r * SEQ + (t + 1) * 16 + c);
                pf[i] = fb[r * NCT + ct];
            }
            #pragma unroll
            for (int i = 0; i < 2; i++) {
                int id = tid + i * 128;
                int r = id >> 4, c = (id & 15) << 2;
                pvv[i] = *(const float4*)(vb + (size_t)((t + 1) * 16 + r) * DIM + c);
            }
        }
        #pragma unroll
        for (int kk = 0; kk < 16; kk += 8) {
            unsigned a[4][4], bf[4][2];
            #pragma unroll
            for (int mi = 0; mi < 4; mi++) {
                int m = wm * 64 + mi * 16;
                a[mi][0] = Ps[cur][kk + qd    ][m + grp    ];
                a[mi][1] = Ps[cur][kk + qd    ][m + grp + 8];
                a[mi][2] = Ps[cur][kk + qd + 4][m + grp    ];
                a[mi][3] = Ps[cur][kk + qd + 4][m + grp + 8];
            }
            #pragma unroll
            for (int ni = 0; ni < 4; ni++) {
                int n = wn * 32 + ni * 8 + grp;
                bf[ni][0] = Vs[cur][kk + qd    ][n];
                bf[ni][1] = Vs[cur][kk + qd + 4][n];
            }
            #pragma unroll
            for (int mi = 0; mi < 4; mi++)
                #pragma unroll
                for (int ni = 0; ni < 4; ni++)
                    mma_tf32(acc[mi][ni], a[mi][0], a[mi][1], a[mi][2], a[mi][3],
                             bf[ni][0], bf[ni][1]);
        }
        if (t + 1 < NK) {
            int nxt = cur ^ 1;
            #pragma unroll
            for (int i = 0; i < 4; i++) {
                int id = tid + i * 128;
                int r  = id >> 2;
                int c  = (id & 3) << 2;
                float4 p = make_float4(pe[i].x * pf[i], pe[i].y * pf[i],
                                       pe[i].z * pf[i], pe[i].w * pf[i]);
                *(float4*)(pb + (size_t)r * SEQ + (t + 1) * 16 + c) = p;
                Ps[nxt][c+0][r] = f2tf(p.x); Ps[nxt][c+1][r] = f2tf(p.y);
                Ps[nxt][c+2][r] = f2tf(p.z); Ps[nxt][c+3][r] = f2tf(p.w);
            }
            #pragma unroll
            for (int i = 0; i < 2; i++) {
                int id = tid + i * 128;
                int r = id >> 4, c = (id & 15) << 2;
                Vs[nxt][r][c+0] = f2tf(pvv[i].x); Vs[nxt][r][c+1] = f2tf(pvv[i].y);
                Vs[nxt][r][c+2] = f2tf(pvv[i].z); Vs[nxt][r][c+3] = f2tf(pvv[i].w);
            }
            __syncthreads();
        }
    }

    float* ob = g_bl + (size_t)b * SEQ * DIM;
    int r0 = row0 + wm * 64;
    int c0 = h * DK + wn * 32;
    #pragma unroll
    for (int mi = 0; mi < 4; mi++) {
        #pragma unroll
        for (int ni = 0; ni < 4; ni++) {
            int r  = r0 + mi * 16 + grp;
            int cc = c0 + ni * 8 + qd * 2;
            *(float2*)(ob + (size_t)r * DIM + cc) =
                make_float2(acc[mi][ni][0], acc[mi][ni][1]);
            *(float2*)(ob + (size_t)(r + 8) * DIM + cc) =
                make_float2(acc[mi][ni][2], acc[mi][ni][3]);
        }
    }
}

// ---------------------------------------------------------------------------
extern "C" void kernel_launch(void* const* d_in, const int* in_sizes, int n_in,
                              void* d_out, int out_size)
{
    const float* query = (const float*)d_in[0];
    const float* key   = (const float*)d_in[1];
    const float* value = (const float*)d_in[2];
    const float* Wq    = (const float*)d_in[3];
    const float* bq    = (const float*)d_in[4];
    const float* Wk    = (const float*)d_in[5];
    const float* bk    = (const float*)d_in[6];
    const float* Wv    = (const float*)d_in[7];
    const float* bv    = (const float*)d_in[8];
    const float* Wo    = (const float*)d_in[9];
    const float* bo    = (const float*)d_in[10];

    float* out   = (float*)d_out;                          // [B,S,D]
    float* score = out + (size_t)BSZ * SEQ * DIM;          // [B,H,S,S]

    float *pq, *pk, *pv, *pbl;
    cudaGetSymbolAddress((void**)&pq,  g_q);
    cudaGetSymbolAddress((void**)&pk,  g_k);
    cudaGetSymbolAddress((void**)&pv,  g_v);
    cudaGetSymbolAddress((void**)&pbl, g_bl);

    cudaFuncSetAttribute(gemm_cpa,
        cudaFuncAttributeMaxDynamicSharedMemorySize, GEMM_SMEM);
    cudaFuncSetAttribute(attn_scores_stats,
        cudaFuncAttributeMaxDynamicSharedMemorySize, SC_SMEM);

    dim3 gp(DIM / 128, MTOT / 128);   // (8, 32)
    gemm_cpa<<<gp, 256, GEMM_SMEM>>>(query, Wq, bq, pq, MTOT, DIM, DIM);
    gemm_cpa<<<gp, 256, GEMM_SMEM>>>(key,   Wk, bk, pk, MTOT, DIM, DIM);
    gemm_cpa<<<gp, 256, GEMM_SMEM>>>(value, Wv, bv, pv, MTOT, DIM, DIM);

    attn_scores_stats<<<dim3(SEQ / 128, SEQ / 128, BH), 256, SC_SMEM>>>(score);
    combine_stats<<<NROWS / 256, 256>>>();
    attn_pv_fused<<<dim3(SEQ / 128, BH), 128>>>(score);

    gemm_cpa<<<gp, 256, GEMM_SMEM>>>(pbl, Wo, bo, out, MTOT, DIM, DIM);
}

// round 8
// speedup vs baseline: 2.2660x; 1.0371x over previous
#include <cuda_runtime.h>
#include <math.h>
#include <stdint.h>

#define BSZ 2
#define SEQ 2048
#define DIM 1024
#define NH  16
#define DK  64
#define BH  (BSZ*NH)   // 32
#define MTOT (BSZ*SEQ) // 4096
#define NROWS (BH*SEQ) // 65536
#define NCT  16        // col tiles of 128 per row

// Scratch (allocation-free rule: __device__ globals)
__device__ float g_q [BSZ*SEQ*DIM];
__device__ float g_k [BSZ*SEQ*DIM];
__device__ float g_v [BSZ*SEQ*DIM];
__device__ float g_bl[BSZ*SEQ*DIM];
__device__ float g_smax  [NROWS*NCT];
__device__ float g_ssum  [NROWS*NCT];
__device__ float g_factor[NROWS*NCT];

// ---------------------------------------------------------------------------
// helpers
// ---------------------------------------------------------------------------
__device__ __forceinline__ unsigned f2tf(float x) {
    unsigned r;
    asm("cvt.rna.tf32.f32 %0, %1;" : "=r"(r) : "f"(x));
    return r;
}

__device__ __forceinline__ void mma_tf32(float c[4],
    unsigned a0, unsigned a1, unsigned a2, unsigned a3,
    unsigned b0, unsigned b1)
{
    asm volatile(
        "mma.sync.aligned.m16n8k8.row.col.f32.tf32.tf32.f32 "
        "{%0,%1,%2,%3}, {%4,%5,%6,%7}, {%8,%9}, {%0,%1,%2,%3};\n"
        : "+f"(c[0]), "+f"(c[1]), "+f"(c[2]), "+f"(c[3])
        : "r"(a0), "r"(a1), "r"(a2), "r"(a3), "r"(b0), "r"(b1));
}

__device__ __forceinline__ unsigned smem_u32(const void* p) {
    unsigned a;
    asm("{ .reg .u64 t; cvta.to.shared.u64 t, %1; cvt.u32.u64 %0, t; }"
        : "=r"(a) : "l"(p));
    return a;
}

#define CPA_COMMIT() asm volatile("cp.async.commit_group;" ::: "memory")
#define CPA_WAIT1()  asm volatile("cp.async.wait_group 1;" ::: "memory")
#define CPA_WAIT0()  asm volatile("cp.async.wait_group 0;" ::: "memory")

#define TPAD 20   // floats per padded row in GEMM tiles

// cp.async one 128x16 f32 tile into padded smem [128][TPAD]; 256 threads.
__device__ __forceinline__ void cpa_tile(
    float (*dst)[TPAD], const float* __restrict__ src, int lda, int tid)
{
    #pragma unroll
    for (int i = 0; i < 2; i++) {
        int id = tid + i * 256;       // 0..511
        int r  = id >> 2;             // 0..127
        int c4 = (id & 3) << 2;       // 0,4,8,12
        unsigned sa = smem_u32(&dst[r][c4]);
        asm volatile("cp.async.cg.shared.global [%0], [%1], 16;"
                     :: "r"(sa), "l"(src + (size_t)r * lda + c4) : "memory");
    }
}

// One 16-K tile of MMAs with in-loop cvt (generic fp32 input).
__device__ __forceinline__ void tile_mma(
    const float (*As)[TPAD], const float (*Bs)[TPAD],
    float acc[4][4][4], int wm, int wn, int grp, int qd)
{
    #pragma unroll
    for (int kk = 0; kk < 16; kk += 8) {
        unsigned a[4][4], b[4][2];
        #pragma unroll
        for (int mi = 0; mi < 4; mi++) {
            int m = wm * 64 + mi * 16;
            a[mi][0] = f2tf(As[m + grp    ][kk + qd    ]);
            a[mi][1] = f2tf(As[m + grp + 8][kk + qd    ]);
            a[mi][2] = f2tf(As[m + grp    ][kk + qd + 4]);
            a[mi][3] = f2tf(As[m + grp + 8][kk + qd + 4]);
        }
        #pragma unroll
        for (int ni = 0; ni < 4; ni++) {
            int n = wn * 32 + ni * 8 + grp;
            b[ni][0] = f2tf(Bs[n][kk + qd    ]);
            b[ni][1] = f2tf(Bs[n][kk + qd + 4]);
        }
        #pragma unroll
        for (int mi = 0; mi < 4; mi++)
            #pragma unroll
            for (int ni = 0; ni < 4; ni++)
                mma_tf32(acc[mi][ni], a[mi][0], a[mi][1], a[mi][2], a[mi][3],
                         b[ni][0], b[ni][1]);
    }
}

// 3-stage cp.async mainloop over nk 16-K tiles (nk >= 3).
__device__ __forceinline__ void cpa_loop(
    const float* __restrict__ A, int lda,
    const float* __restrict__ B, int ldb, int nk,
    float (*As)[128][TPAD], float (*Bs)[128][TPAD],
    float acc[4][4][4], int tid, int wm, int wn, int grp, int qd)
{
    cpa_tile(As[0], A, lda, tid);
    cpa_tile(Bs[0], B, ldb, tid);
    CPA_COMMIT();
    cpa_tile(As[1], A + 16, lda, tid);
    cpa_tile(Bs[1], B + 16, ldb, tid);
    CPA_COMMIT();

    int cur = 0;
    for (int t = 0; t < nk; t++) {
        if (t < nk - 1) CPA_WAIT1(); else CPA_WAIT0();
        __syncthreads();
        tile_mma(As[cur], Bs[cur], acc, wm, wn, grp, qd);
        if (t + 2 < nk) {
            int nxt = cur + 2; if (nxt >= 3) nxt -= 3;
            cpa_tile(As[nxt], A + (t + 2) * 16, lda, tid);
            cpa_tile(Bs[nxt], B + (t + 2) * 16, ldb, tid);
            CPA_COMMIT();
        }
        if (++cur == 3) cur = 0;
    }
}

#define GEMM_SMEM (3 * 128 * TPAD * 4 * 2)          // 61440

// ---------------------------------------------------------------------------
// GEMM: C[M,N] = A[M,K] @ W[N,K]^T + bias[N]; CTA 128x128, 256 thr.
// round_out: store tf32-rounded bit patterns (for q/k/v, bit-identical to
// what consumers would produce via cvt).
// ---------------------------------------------------------------------------
__global__ __launch_bounds__(256, 2) void gemm_cpa(
    const float* __restrict__ A, const float* __restrict__ W,
    const float* __restrict__ bias, float* __restrict__ C,
    int M, int N, int K, int round_out)
{
    extern __shared__ float sm[];
    float (*As)[128][TPAD] = (float (*)[128][TPAD])sm;
    float (*Bs)[128][TPAD] = (float (*)[128][TPAD])(sm + 3 * 128 * TPAD);

    int tid = threadIdx.x;
    int warp = tid >> 5, lane = tid & 31;
    int wm = warp >> 2, wn = warp & 3;
    int grp = lane >> 2, qd = lane & 3;

    const float* Ab = A + (size_t)(blockIdx.y * 128) * K;
    const float* Wb = W + (size_t)(blockIdx.x * 128) * K;
    float acc[4][4][4] = {};
    cpa_loop(Ab, K, Wb, K, K / 16, As, Bs, acc, tid, wm, wn, grp, qd);

    int row0 = blockIdx.y * 128 + wm * 64;
    int col0 = blockIdx.x * 128 + wn * 32;
    #pragma unroll
    for (int mi = 0; mi < 4; mi++) {
        #pragma unroll
        for (int ni = 0; ni < 4; ni++) {
            int r  = row0 + mi * 16 + grp;
            int cc = col0 + ni * 8 + qd * 2;
            float b0 = bias[cc], b1 = bias[cc + 1];
            float v00 = acc[mi][ni][0] + b0, v01 = acc[mi][ni][1] + b1;
            float v10 = acc[mi][ni][2] + b0, v11 = acc[mi][ni][3] + b1;
            if (round_out) {
                v00 = __uint_as_float(f2tf(v00)); v01 = __uint_as_float(f2tf(v01));
                v10 = __uint_as_float(f2tf(v10)); v11 = __uint_as_float(f2tf(v11));
            }
            *(float2*)(C + (size_t)r * N + cc)       = make_float2(v00, v01);
            *(float2*)(C + (size_t)(r + 8) * N + cc) = make_float2(v10, v11);
        }
    }
}

// ---------------------------------------------------------------------------
// scores v3: Q,K tiles fully resident (K=64), no cvt (inputs pre-rounded),
// no pipeline. e = exp(x/8 - m_tile); per-row-tile (max,sum) partials.
// ---------------------------------------------------------------------------
#define QPAD 68
#define SC_SMEM (2 * 128 * QPAD * 4)   // 69632

__global__ __launch_bounds__(256, 2) void attn_scores_v3(float* __restrict__ score)
{
    extern __shared__ float sm[];
    float (*Qs)[QPAD] = (float (*)[QPAD])sm;
    float (*Ks)[QPAD] = (float (*)[QPAD])(sm + 128 * QPAD);
    float (*rstat)[4] = (float (*)[4])sm;   // reuse after mainloop

    int tid = threadIdx.x;
    int warp = tid >> 5, lane = tid & 31;
    int wm = warp >> 2, wn = warp & 3;
    int grp = lane >> 2, qd = lane & 3;
    int bh = blockIdx.z, b = bh >> 4, h = bh & 15;

    const float* qb = g_q + (size_t)b * SEQ * DIM + (size_t)(blockIdx.y * 128) * DIM + h * DK;
    const float* kb = g_k + (size_t)b * SEQ * DIM + (size_t)(blockIdx.x * 128) * DIM + h * DK;

    // single-shot loads: 128 rows x 64 floats = 2048 float4 per tile
    #pragma unroll
    for (int i = 0; i < 8; i++) {
        int id = tid + i * 256;       // 0..2047
        int r  = id >> 4;             // 0..127
        int c4 = (id & 15) << 2;      // 0..60
        unsigned sa = smem_u32(&Qs[r][c4]);
        asm volatile("cp.async.cg.shared.global [%0], [%1], 16;"
                     :: "r"(sa), "l"(qb + (size_t)r * DIM + c4) : "memory");
    }
    #pragma unroll
    for (int i = 0; i < 8; i++) {
        int id = tid + i * 256;
        int r  = id >> 4;
        int c4 = (id & 15) << 2;
        unsigned sa = smem_u32(&Ks[r][c4]);
        asm volatile("cp.async.cg.shared.global [%0], [%1], 16;"
                     :: "r"(sa), "l"(kb + (size_t)r * DIM + c4) : "memory");
    }
    CPA_COMMIT();
    CPA_WAIT0();
    __syncthreads();

    float acc[4][4][4] = {};
    #pragma unroll
    for (int kk8 = 0; kk8 < 64; kk8 += 8) {
        unsigned a[4][4], bf[4][2];
        #pragma unroll
        for (int mi = 0; mi < 4; mi++) {
            int m = wm * 64 + mi * 16;
            a[mi][0] = __float_as_uint(Qs[m + grp    ][kk8 + qd    ]);
            a[mi][1] = __float_as_uint(Qs[m + grp + 8][kk8 + qd    ]);
            a[mi][2] = __float_as_uint(Qs[m + grp    ][kk8 + qd + 4]);
            a[mi][3] = __float_as_uint(Qs[m + grp + 8][kk8 + qd + 4]);
        }
        #pragma unroll
        for (int ni = 0; ni < 4; ni++) {
            int n = wn * 32 + ni * 8 + grp;
            bf[ni][0] = __float_as_uint(Ks[n][kk8 + qd    ]);
            bf[ni][1] = __float_as_uint(Ks[n][kk8 + qd + 4]);
        }
        #pragma unroll
        for (int mi = 0; mi < 4; mi++)
            #pragma unroll
            for (int ni = 0; ni < 4; ni++)
                mma_tf32(acc[mi][ni], a[mi][0], a[mi][1], a[mi][2], a[mi][3],
                         bf[ni][0], bf[ni][1]);
    }
    __syncthreads();   // tiles dead; rstat aliases smem

    const float alpha = 0.125f;
    #pragma unroll
    for (int mi = 0; mi < 4; mi++)
        #pragma unroll
        for (int ni = 0; ni < 4; ni++)
            #pragma unroll
            for (int j = 0; j < 4; j++)
                acc[mi][ni][j] *= alpha;

    float msel[4][2];
    #pragma unroll
    for (int mi = 0; mi < 4; mi++) {
        float mA = -1e30f, mB = -1e30f;
        #pragma unroll
        for (int ni = 0; ni < 4; ni++) {
            mA = fmaxf(mA, fmaxf(acc[mi][ni][0], acc[mi][ni][1]));
            mB = fmaxf(mB, fmaxf(acc[mi][ni][2], acc[mi][ni][3]));
        }
        mA = fmaxf(mA, __shfl_xor_sync(0xffffffffu, mA, 1));
        mA = fmaxf(mA, __shfl_xor_sync(0xffffffffu, mA, 2));
        mB = fmaxf(mB, __shfl_xor_sync(0xffffffffu, mB, 1));
        mB = fmaxf(mB, __shfl_xor_sync(0xffffffffu, mB, 2));
        int rA = wm * 64 + mi * 16 + grp;
        if (qd == 0) { rstat[rA][wn] = mA; rstat[rA + 8][wn] = mB; }
    }
    __syncthreads();
    #pragma unroll
    for (int mi = 0; mi < 4; mi++) {
        int rA = wm * 64 + mi * 16 + grp;
        msel[mi][0] = fmaxf(fmaxf(rstat[rA][0],     rstat[rA][1]),
                            fmaxf(rstat[rA][2],     rstat[rA][3]));
        msel[mi][1] = fmaxf(fmaxf(rstat[rA + 8][0], rstat[rA + 8][1]),
                            fmaxf(rstat[rA + 8][2], rstat[rA + 8][3]));
    }
    __syncthreads();

    float ssel[4][2];
    #pragma unroll
    for (int mi = 0; mi < 4; mi++) {
        float sA = 0.f, sB = 0.f;
        #pragma unroll
        for (int ni = 0; ni < 4; ni++) {
            acc[mi][ni][0] = __expf(acc[mi][ni][0] - msel[mi][0]);
            acc[mi][ni][1] = __expf(acc[mi][ni][1] - msel[mi][0]);
            acc[mi][ni][2] = __expf(acc[mi][ni][2] - msel[mi][1]);
            acc[mi][ni][3] = __expf(acc[mi][ni][3] - msel[mi][1]);
            sA += acc[mi][ni][0] + acc[mi][ni][1];
            sB += acc[mi][ni][2] + acc[mi][ni][3];
        }
        sA += __shfl_xor_sync(0xffffffffu, sA, 1);
        sA += __shfl_xor_sync(0xffffffffu, sA, 2);
        sB += __shfl_xor_sync(0xffffffffu, sB, 1);
        sB += __shfl_xor_sync(0xffffffffu, sB, 2);
        int rA = wm * 64 + mi * 16 + grp;
        if (qd == 0) { rstat[rA][wn] = sA; rstat[rA + 8][wn] = sB; }
    }
    __syncthreads();
    #pragma unroll
    for (int mi = 0; mi < 4; mi++) {
        int rA = wm * 64 + mi * 16 + grp;
        ssel[mi][0] = (rstat[rA][0]     + rstat[rA][1])
                    + (rstat[rA][2]     + rstat[rA][3]);
        ssel[mi][1] = (rstat[rA + 8][0] + rstat[rA + 8][1])
                    + (rstat[rA + 8][2] + rstat[rA + 8][3]);
    }

    float* ob = score + (size_t)bh * SEQ * SEQ;
    int row0 = blockIdx.y * 128 + wm * 64;
    int col0 = blockIdx.x * 128 + wn * 32;
    #pragma unroll
    for (int mi = 0; mi < 4; mi++) {
        #pragma unroll
        for (int ni = 0; ni < 4; ni++) {
            int r  = row0 + mi * 16 + grp;
            int cc = col0 + ni * 8 + qd * 2;
            *(float2*)(ob + (size_t)r * SEQ + cc) =
                make_float2(acc[mi][ni][0], acc[mi][ni][1]);
            *(float2*)(ob + (size_t)(r + 8) * SEQ + cc) =
                make_float2(acc[mi][ni][2], acc[mi][ni][3]);
        }
    }

    if (wn == 0 && qd == 0) {
        #pragma unroll
        for (int mi = 0; mi < 4; mi++) {
            #pragma unroll
            for (int half = 0; half < 2; half++) {
                int rowg = blockIdx.y * 128 + wm * 64 + mi * 16 + half * 8 + grp;
                size_t idx = ((size_t)(bh << 11) + rowg) * NCT + blockIdx.x;
                g_smax[idx] = msel[mi][half];
                g_ssum[idx] = ssel[mi][half];
            }
        }
    }
}

// ---------------------------------------------------------------------------
__global__ __launch_bounds__(256) void combine_stats()
{
    int gid = blockIdx.x * 256 + threadIdx.x;
    const float* mx = g_smax + (size_t)gid * NCT;
    const float* smv = g_ssum + (size_t)gid * NCT;
    float mv[NCT];
    float m = -1e30f;
    #pragma unroll
    for (int i = 0; i < NCT; i++) { mv[i] = mx[i]; m = fmaxf(m, mv[i]); }
    float s = 0.f;
    float ev[NCT];
    #pragma unroll
    for (int i = 0; i < NCT; i++) { ev[i] = __expf(mv[i] - m); s += smv[i] * ev[i]; }
    float inv = 1.0f / s;
    #pragma unroll
    for (int i = 0; i < NCT; i++) g_factor[(size_t)gid * NCT + i] = ev[i] * inv;
}

// ---------------------------------------------------------------------------
// PV fused: p = e*factor written in place, blended = P @ V.
// 128 threads, warps 2x2, warp tile 64x32. V pre-rounded (no cvt at STS).
// ---------------------------------------------------------------------------
__global__ __launch_bounds__(128, 2) void attn_pv_fused(float* __restrict__ score)
{
    __shared__ unsigned Ps[2][16][136];
    __shared__ unsigned Vs[2][16][72];
    int tid = threadIdx.x;
    int bh = blockIdx.y, b = bh >> 4, h = bh & 15;
    int row0 = blockIdx.x * 128;
    float* pb = score + (size_t)bh * SEQ * SEQ + (size_t)row0 * SEQ;
    const float* vb = g_v + (size_t)b * SEQ * DIM + h * DK;
    const float* fb = g_factor + ((size_t)(bh << 11) + row0) * NCT;

    int warp = tid >> 5, lane = tid & 31;
    int wm = warp >> 1, wn = warp & 1;
    int grp = lane >> 2, qd = lane & 3;
    float acc[4][4][4] = {};

    float4 pe[4]; float pf[4]; float4 pvv[2];

    #pragma unroll
    for (int i = 0; i < 4; i++) {
        int id = tid + i * 128;
        int r  = id >> 2;
        int c  = (id & 3) << 2;
        pe[i] = *(const float4*)(pb + (size_t)r * SEQ + c);
        pf[i] = fb[r * NCT + 0];
    }
    #pragma unroll
    for (int i = 0; i < 2; i++) {
        int id = tid + i * 128;
        int r = id >> 4, c = (id & 15) << 2;
        pvv[i] = *(const float4*)(vb + (size_t)r * DIM + c);
    }
    #pragma unroll
    for (int i = 0; i < 4; i++) {
        int id = tid + i * 128;
        int r  = id >> 2;
        int c  = (id & 3) << 2;
        float4 p = make_float4(pe[i].x * pf[i], pe[i].y * pf[i],
                               pe[i].z * pf[i], pe[i].w * pf[i]);
        *(float4*)(pb + (size_t)r * SEQ + c) = p;
        Ps[0][c+0][r] = f2tf(p.x); Ps[0][c+1][r] = f2tf(p.y);
        Ps[0][c+2][r] = f2tf(p.z); Ps[0][c+3][r] = f2tf(p.w);
    }
    #pragma unroll
    for (int i = 0; i < 2; i++) {
        int id = tid + i * 128;
        int r = id >> 4, c = (id & 15) << 2;
        Vs[0][r][c+0] = __float_as_uint(pvv[i].x); Vs[0][r][c+1] = __float_as_uint(pvv[i].y);
        Vs[0][r][c+2] = __float_as_uint(pvv[i].z); Vs[0][r][c+3] = __float_as_uint(pvv[i].w);
    }
    __syncthreads();

    const int NK = SEQ / 16;
    for (int t = 0; t < NK; t++) {
        int cur = t & 1;
        if (t + 1 < NK) {
            int ct = (t + 1) >> 3;
            #pragma unroll
            for (int i = 0; i < 4; i++) {
                int id = tid + i * 128;
                int r  = id >> 2;
                int c  = (id & 3) << 2;
                pe[i] = *(const float4*)(pb + (size_t)r * SEQ + (t + 1) * 16 + c);
                pf[i] = fb[r * NCT + ct];
            }
            #pragma unroll
            for (int i = 0; i < 2; i++) {
                int id = tid + i * 128;
                int r = id >> 4, c = (id & 15) << 2;
                pvv[i] = *(const float4*)(vb + (size_t)((t + 1) * 16 + r) * DIM + c);
            }
        }
        #pragma unroll
        for (int kk = 0; kk < 16; kk += 8) {
            unsigned a[4][4], bf[4][2];
            #pragma unroll
            for (int mi = 0; mi < 4; mi++) {
                int m = wm * 64 + mi * 16;
                a[mi][0] = Ps[cur][kk + qd    ][m + grp    ];
                a[mi][1] = Ps[cur][kk + qd    ][m + grp + 8];
                a[mi][2] = Ps[cur][kk + qd + 4][m + grp    ];
                a[mi][3] = Ps[cur][kk + qd + 4][m + grp + 8];
            }
            #pragma unroll
            for (int ni = 0; ni < 4; ni++) {
                int n = wn * 32 + ni * 8 + grp;
                bf[ni][0] = Vs[cur][kk + qd    ][n];
                bf[ni][1] = Vs[cur][kk + qd + 4][n];
            }
            #pragma unroll
            for (int mi = 0; mi < 4; mi++)
                #pragma unroll
                for (int ni = 0; ni < 4; ni++)
                    mma_tf32(acc[mi][ni], a[mi][0], a[mi][1], a[mi][2], a[mi][3],
                             bf[ni][0], bf[ni][1]);
        }
        if (t + 1 < NK) {
            int nxt = cur ^ 1;
            #pragma unroll
            for (int i = 0; i < 4; i++) {
                int id = tid + i * 128;
                int r  = id >> 2;
                int c  = (id & 3) << 2;
                float4 p = make_float4(pe[i].x * pf[i], pe[i].y * pf[i],
                                       pe[i].z * pf[i], pe[i].w * pf[i]);
                *(float4*)(pb + (size_t)r * SEQ + (t + 1) * 16 + c) = p;
                Ps[nxt][c+0][r] = f2tf(p.x); Ps[nxt][c+1][r] = f2tf(p.y);
                Ps[nxt][c+2][r] = f2tf(p.z); Ps[nxt][c+3][r] = f2tf(p.w);
            }
            #pragma unroll
            for (int i = 0; i < 2; i++) {
                int id = tid + i * 128;
                int r = id >> 4, c = (id & 15) << 2;
                Vs[nxt][r][c+0] = __float_as_uint(pvv[i].x); Vs[nxt][r][c+1] = __float_as_uint(pvv[i].y);
                Vs[nxt][r][c+2] = __float_as_uint(pvv[i].z); Vs[nxt][r][c+3] = __float_as_uint(pvv[i].w);
            }
            __syncthreads();
        }
    }

    float* ob = g_bl + (size_t)b * SEQ * DIM;
    int r0 = row0 + wm * 64;
    int c0 = h * DK + wn * 32;
    #pragma unroll
    for (int mi = 0; mi < 4; mi++) {
        #pragma unroll
        for (int ni = 0; ni < 4; ni++) {
            int r  = r0 + mi * 16 + grp;
            int cc = c0 + ni * 8 + qd * 2;
            *(float2*)(ob + (size_t)r * DIM + cc) =
                make_float2(acc[mi][ni][0], acc[mi][ni][1]);
            *(float2*)(ob + (size_t)(r + 8) * DIM + cc) =
                make_float2(acc[mi][ni][2], acc[mi][ni][3]);
        }
    }
}

// ---------------------------------------------------------------------------
extern "C" void kernel_launch(void* const* d_in, const int* in_sizes, int n_in,
                              void* d_out, int out_size)
{
    const float* query = (const float*)d_in[0];
    const float* key   = (const float*)d_in[1];
    const float* value = (const float*)d_in[2];
    const float* Wq    = (const float*)d_in[3];
    const float* bq    = (const float*)d_in[4];
    const float* Wk    = (const float*)d_in[5];
    const float* bk    = (const float*)d_in[6];
    const float* Wv    = (const float*)d_in[7];
    const float* bv    = (const float*)d_in[8];
    const float* Wo    = (const float*)d_in[9];
    const float* bo    = (const float*)d_in[10];

    float* out   = (float*)d_out;                          // [B,S,D]
    float* score = out + (size_t)BSZ * SEQ * DIM;          // [B,H,S,S]

    float *pq, *pk, *pv, *pbl;
    cudaGetSymbolAddress((void**)&pq,  g_q);
    cudaGetSymbolAddress((void**)&pk,  g_k);
    cudaGetSymbolAddress((void**)&pv,  g_v);
    cudaGetSymbolAddress((void**)&pbl, g_bl);

    cudaFuncSetAttribute(gemm_cpa,
        cudaFuncAttributeMaxDynamicSharedMemorySize, GEMM_SMEM);
    cudaFuncSetAttribute(attn_scores_v3,
        cudaFuncAttributeMaxDynamicSharedMemorySize, SC_SMEM);

    dim3 gp(DIM / 128, MTOT / 128);   // (8, 32)
    gemm_cpa<<<gp, 256, GEMM_SMEM>>>(query, Wq, bq, pq, MTOT, DIM, DIM, 1);
    gemm_cpa<<<gp, 256, GEMM_SMEM>>>(key,   Wk, bk, pk, MTOT, DIM, DIM, 1);
    gemm_cpa<<<gp, 256, GEMM_SMEM>>>(value, Wv, bv, pv, MTOT, DIM, DIM, 1);

    attn_scores_v3<<<dim3(SEQ / 128, SEQ / 128, BH), 256, SC_SMEM>>>(score);
    combine_stats<<<NROWS / 256, 256>>>();
    attn_pv_fused<<<dim3(SEQ / 128, BH), 128>>>(score);

    gemm_cpa<<<gp, 256, GEMM_SMEM>>>(pbl, Wo, bo, out, MTOT, DIM, DIM, 0);
}

// round 10
// speedup vs baseline: 2.2957x; 1.0131x over previous
#include <cuda_runtime.h>
#include <math.h>
#include <stdint.h>

#define BSZ 2
#define SEQ 2048
#define DIM 1024
#define NH  16
#define DK  64
#define BH  (BSZ*NH)   // 32
#define MTOT (BSZ*SEQ) // 4096
#define NROWS (BH*SEQ) // 65536
#define NCT  16        // col tiles of 128 per row

// Scratch (allocation-free rule: __device__ globals)
__device__ float g_q [BSZ*SEQ*DIM];
__device__ float g_k [BSZ*SEQ*DIM];
__device__ float g_v [BSZ*SEQ*DIM];
__device__ float g_bl[BSZ*SEQ*DIM];
__device__ float g_smax  [NROWS*NCT];
__device__ float g_ssum  [NROWS*NCT];
__device__ float g_factor[NROWS*NCT];

// ---------------------------------------------------------------------------
// helpers
// ---------------------------------------------------------------------------
__device__ __forceinline__ unsigned f2tf(float x) {
    unsigned r;
    asm("cvt.rna.tf32.f32 %0, %1;" : "=r"(r) : "f"(x));
    return r;
}

__device__ __forceinline__ void mma_tf32(float c[4],
    unsigned a0, unsigned a1, unsigned a2, unsigned a3,
    unsigned b0, unsigned b1)
{
    asm volatile(
        "mma.sync.aligned.m16n8k8.row.col.f32.tf32.tf32.f32 "
        "{%0,%1,%2,%3}, {%4,%5,%6,%7}, {%8,%9}, {%0,%1,%2,%3};\n"
        : "+f"(c[0]), "+f"(c[1]), "+f"(c[2]), "+f"(c[3])
        : "r"(a0), "r"(a1), "r"(a2), "r"(a3), "r"(b0), "r"(b1));
}

__device__ __forceinline__ unsigned smem_u32(const void* p) {
    unsigned a;
    asm("{ .reg .u64 t; cvta.to.shared.u64 t, %1; cvt.u32.u64 %0, t; }"
        : "=r"(a) : "l"(p));
    return a;
}

#define CPA_COMMIT() asm volatile("cp.async.commit_group;" ::: "memory")
#define CPA_WAIT1()  asm volatile("cp.async.wait_group 1;" ::: "memory")
#define CPA_WAIT0()  asm volatile("cp.async.wait_group 0;" ::: "memory")

__device__ __forceinline__ void cpa16(const void* smem_dst, const float* gsrc) {
    unsigned sa = smem_u32(smem_dst);
    asm volatile("cp.async.cg.shared.global [%0], [%1], 16;"
                 :: "r"(sa), "l"(gsrc) : "memory");
}

#define TPAD 20   // floats per padded row in GEMM tiles

// cp.async one 128x16 f32 tile into padded smem [128][TPAD]; 256 threads.
__device__ __forceinline__ void cpa_tile(
    float (*dst)[TPAD], const float* __restrict__ src, int lda, int tid)
{
    #pragma unroll
    for (int i = 0; i < 2; i++) {
        int id = tid + i * 256;       // 0..511
        int r  = id >> 2;             // 0..127
        int c4 = (id & 3) << 2;       // 0,4,8,12
        cpa16(&dst[r][c4], src + (size_t)r * lda + c4);
    }
}

// One 16-K tile of MMAs with in-loop cvt (generic fp32 input).
__device__ __forceinline__ void tile_mma(
    const float (*As)[TPAD], const float (*Bs)[TPAD],
    float acc[4][4][4], int wm, int wn, int grp, int qd)
{
    #pragma unroll
    for (int kk = 0; kk < 16; kk += 8) {
        unsigned a[4][4], b[4][2];
        #pragma unroll
        for (int mi = 0; mi < 4; mi++) {
            int m = wm * 64 + mi * 16;
            a[mi][0] = f2tf(As[m + grp    ][kk + qd    ]);
            a[mi][1] = f2tf(As[m + grp + 8][kk + qd    ]);
            a[mi][2] = f2tf(As[m + grp    ][kk + qd + 4]);
            a[mi][3] = f2tf(As[m + grp + 8][kk + qd + 4]);
        }
        #pragma unroll
        for (int ni = 0; ni < 4; ni++) {
            int n = wn * 32 + ni * 8 + grp;
            b[ni][0] = f2tf(Bs[n][kk + qd    ]);
            b[ni][1] = f2tf(Bs[n][kk + qd + 4]);
        }
        #pragma unroll
        for (int mi = 0; mi < 4; mi++)
            #pragma unroll
            for (int ni = 0; ni < 4; ni++)
                mma_tf32(acc[mi][ni], a[mi][0], a[mi][1], a[mi][2], a[mi][3],
                         b[ni][0], b[ni][1]);
    }
}

// 3-stage cp.async mainloop over nk 16-K tiles (nk >= 3).
__device__ __forceinline__ void cpa_loop(
    const float* __restrict__ A, int lda,
    const float* __restrict__ B, int ldb, int nk,
    float (*As)[128][TPAD], float (*Bs)[128][TPAD],
    float acc[4][4][4], int tid, int wm, int wn, int grp, int qd)
{
    cpa_tile(As[0], A, lda, tid);
    cpa_tile(Bs[0], B, ldb, tid);
    CPA_COMMIT();
    cpa_tile(As[1], A + 16, lda, tid);
    cpa_tile(Bs[1], B + 16, ldb, tid);
    CPA_COMMIT();

    int cur = 0;
    for (int t = 0; t < nk; t++) {
        if (t < nk - 1) CPA_WAIT1(); else CPA_WAIT0();
        __syncthreads();
        tile_mma(As[cur], Bs[cur], acc, wm, wn, grp, qd);
        if (t + 2 < nk) {
            int nxt = cur + 2; if (nxt >= 3) nxt -= 3;
            cpa_tile(As[nxt], A + (t + 2) * 16, lda, tid);
            cpa_tile(Bs[nxt], B + (t + 2) * 16, ldb, tid);
            CPA_COMMIT();
        }
        if (++cur == 3) cur = 0;
    }
}

#define GEMM_SMEM (3 * 128 * TPAD * 4 * 2)          // 61440

// ---------------------------------------------------------------------------
// GEMM: C[M,N] = A[M,K] @ W[N,K]^T + bias[N]; CTA 128x128, 256 thr.
// ---------------------------------------------------------------------------
__global__ __launch_bounds__(256, 2) void gemm_cpa(
    const float* __restrict__ A, const float* __restrict__ W,
    const float* __restrict__ bias, float* __restrict__ C,
    int M, int N, int K, int round_out)
{
    extern __shared__ float sm[];
    float (*As)[128][TPAD] = (float (*)[128][TPAD])sm;
    float (*Bs)[128][TPAD] = (float (*)[128][TPAD])(sm + 3 * 128 * TPAD);

    int tid = threadIdx.x;
    int warp = tid >> 5, lane = tid & 31;
    int wm = warp >> 2, wn = warp & 3;
    int grp = lane >> 2, qd = lane & 3;

    const float* Ab = A + (size_t)(blockIdx.y * 128) * K;
    const float* Wb = W + (size_t)(blockIdx.x * 128) * K;
    float acc[4][4][4] = {};
    cpa_loop(Ab, K, Wb, K, K / 16, As, Bs, acc, tid, wm, wn, grp, qd);

    int row0 = blockIdx.y * 128 + wm * 64;
    int col0 = blockIdx.x * 128 + wn * 32;
    #pragma unroll
    for (int mi = 0; mi < 4; mi++) {
        #pragma unroll
        for (int ni = 0; ni < 4; ni++) {
            int r  = row0 + mi * 16 + grp;
            int cc = col0 + ni * 8 + qd * 2;
            float b0 = bias[cc], b1 = bias[cc + 1];
            float v00 = acc[mi][ni][0] + b0, v01 = acc[mi][ni][1] + b1;
            float v10 = acc[mi][ni][2] + b0, v11 = acc[mi][ni][3] + b1;
            if (round_out) {
                v00 = __uint_as_float(f2tf(v00)); v01 = __uint_as_float(f2tf(v01));
                v10 = __uint_as_float(f2tf(v10)); v11 = __uint_as_float(f2tf(v11));
            }
            *(float2*)(C + (size_t)r * N + cc)       = make_float2(v00, v01);
            *(float2*)(C + (size_t)(r + 8) * N + cc) = make_float2(v10, v11);
        }
    }
}

// ---------------------------------------------------------------------------
// Phase 1: stats only. QK tile MMA, per-row-tile (max, sumexp). NO e write.
// ---------------------------------------------------------------------------
#define QPAD 68
#define SC_SMEM (2 * 128 * QPAD * 4)   // 69632

__global__ __launch_bounds__(256, 2) void attn_stats()
{
    extern __shared__ float sm[];
    float (*Qs)[QPAD] = (float (*)[QPAD])sm;
    float (*Ks)[QPAD] = (float (*)[QPAD])(sm + 128 * QPAD);
    float (*rstat)[4] = (float (*)[4])sm;   // reuse after mainloop

    int tid = threadIdx.x;
    int warp = tid >> 5, lane = tid & 31;
    int wm = warp >> 2, wn = warp & 3;
    int grp = lane >> 2, qd = lane & 3;
    int bh = blockIdx.z, b = bh >> 4, h = bh & 15;

    const float* qb = g_q + (size_t)b * SEQ * DIM + (size_t)(blockIdx.y * 128) * DIM + h * DK;
    const float* kb = g_k + (size_t)b * SEQ * DIM + (size_t)(blockIdx.x * 128) * DIM + h * DK;

    #pragma unroll
    for (int i = 0; i < 8; i++) {
        int id = tid + i * 256;
        int r  = id >> 4;
        int c4 = (id & 15) << 2;
        cpa16(&Qs[r][c4], qb + (size_t)r * DIM + c4);
    }
    #pragma unroll
    for (int i = 0; i < 8; i++) {
        int id = tid + i * 256;
        int r  = id >> 4;
        int c4 = (id & 15) << 2;
        cpa16(&Ks[r][c4], kb + (size_t)r * DIM + c4);
    }
    CPA_COMMIT();
    CPA_WAIT0();
    __syncthreads();

    float acc[4][4][4] = {};
    #pragma unroll
    for (int kk8 = 0; kk8 < 64; kk8 += 8) {
        unsigned a[4][4], bf[4][2];
        #pragma unroll
        for (int mi = 0; mi < 4; mi++) {
            int m = wm * 64 + mi * 16;
            a[mi][0] = __float_as_uint(Qs[m + grp    ][kk8 + qd    ]);
            a[mi][1] = __float_as_uint(Qs[m + grp + 8][kk8 + qd    ]);
            a[mi][2] = __float_as_uint(Qs[m + grp    ][kk8 + qd + 4]);
            a[mi][3] = __float_as_uint(Qs[m + grp + 8][kk8 + qd + 4]);
        }
        #pragma unroll
        for (int ni = 0; ni < 4; ni++) {
            int n = wn * 32 + ni * 8 + grp;
            bf[ni][0] = __float_as_uint(Ks[n][kk8 + qd    ]);
            bf[ni][1] = __float_as_uint(Ks[n][kk8 + qd + 4]);
        }
        #pragma unroll
        for (int mi = 0; mi < 4; mi++)
            #pragma unroll
            for (int ni = 0; ni < 4; ni++)
                mma_tf32(acc[mi][ni], a[mi][0], a[mi][1], a[mi][2], a[mi][3],
                         bf[ni][0], bf[ni][1]);
    }
    __syncthreads();

    const float alpha = 0.125f;
    #pragma unroll
    for (int mi = 0; mi < 4; mi++)
        #pragma unroll
        for (int ni = 0; ni < 4; ni++)
            #pragma unroll
            for (int j = 0; j < 4; j++)
                acc[mi][ni][j] *= alpha;

    float msel[4][2];
    #pragma unroll
    for (int mi = 0; mi < 4; mi++) {
        float mA = -1e30f, mB = -1e30f;
        #pragma unroll
        for (int ni = 0; ni < 4; ni++) {
            mA = fmaxf(mA, fmaxf(acc[mi][ni][0], acc[mi][ni][1]));
            mB = fmaxf(mB, fmaxf(acc[mi][ni][2], acc[mi][ni][3]));
        }
        mA = fmaxf(mA, __shfl_xor_sync(0xffffffffu, mA, 1));
        mA = fmaxf(mA, __shfl_xor_sync(0xffffffffu, mA, 2));
        mB = fmaxf(mB, __shfl_xor_sync(0xffffffffu, mB, 1));
        mB = fmaxf(mB, __shfl_xor_sync(0xffffffffu, mB, 2));
        int rA = wm * 64 + mi * 16 + grp;
        if (qd == 0) { rstat[rA][wn] = mA; rstat[rA + 8][wn] = mB; }
    }
    __syncthreads();
    #pragma unroll
    for (int mi = 0; mi < 4; mi++) {
        int rA = wm * 64 + mi * 16 + grp;
        msel[mi][0] = fmaxf(fmaxf(rstat[rA][0],     rstat[rA][1]),
                            fmaxf(rstat[rA][2],     rstat[rA][3]));
        msel[mi][1] = fmaxf(fmaxf(rstat[rA + 8][0], rstat[rA + 8][1]),
                            fmaxf(rstat[rA + 8][2], rstat[rA + 8][3]));
    }
    __syncthreads();

    float ssel[4][2];
    #pragma unroll
    for (int mi = 0; mi < 4; mi++) {
        float sA = 0.f, sB = 0.f;
        #pragma unroll
        for (int ni = 0; ni < 4; ni++) {
            sA += __expf(acc[mi][ni][0] - msel[mi][0]);
            sA += __expf(acc[mi][ni][1] - msel[mi][0]);
            sB += __expf(acc[mi][ni][2] - msel[mi][1]);
            sB += __expf(acc[mi][ni][3] - msel[mi][1]);
        }
        sA += __shfl_xor_sync(0xffffffffu, sA, 1);
        sA += __shfl_xor_sync(0xffffffffu, sA, 2);
        sB += __shfl_xor_sync(0xffffffffu, sB, 1);
        sB += __shfl_xor_sync(0xffffffffu, sB, 2);
        int rA = wm * 64 + mi * 16 + grp;
        if (qd == 0) { rstat[rA][wn] = sA; rstat[rA + 8][wn] = sB; }
    }
    __syncthreads();
    #pragma unroll
    for (int mi = 0; mi < 4; mi++) {
        int rA = wm * 64 + mi * 16 + grp;
        ssel[mi][0] = (rstat[rA][0]     + rstat[rA][1])
                    + (rstat[rA][2]     + rstat[rA][3]);
        ssel[mi][1] = (rstat[rA + 8][0] + rstat[rA + 8][1])
                    + (rstat[rA + 8][2] + rstat[rA + 8][3]);
    }

    if (wn == 0 && qd == 0) {
        #pragma unroll
        for (int mi = 0; mi < 4; mi++) {
            #pragma unroll
            for (int half = 0; half < 2; half++) {
                int rowg = blockIdx.y * 128 + wm * 64 + mi * 16 + half * 8 + grp;
                size_t idx = ((size_t)(bh << 11) + rowg) * NCT + blockIdx.x;
                g_smax[idx] = msel[mi][half];
                g_ssum[idx] = ssel[mi][half];
            }
        }
    }
}

// ---------------------------------------------------------------------------
__global__ __launch_bounds__(256) void combine_stats()
{
    int gid = blockIdx.x * 256 + threadIdx.x;
    const float* mx = g_smax + (size_t)gid * NCT;
    const float* smv = g_ssum + (size_t)gid * NCT;
    float mv[NCT];
    float m = -1e30f;
    #pragma unroll
    for (int i = 0; i < NCT; i++) { mv[i] = mx[i]; m = fmaxf(m, mv[i]); }
    float s = 0.f;
    float ev[NCT];
    #pragma unroll
    for (int i = 0; i < NCT; i++) { ev[i] = __expf(mv[i] - m); s += smv[i] * ev[i]; }
    float inv = 1.0f / s;
    #pragma unroll
    for (int i = 0; i < NCT; i++) g_factor[(size_t)gid * NCT + i] = ev[i] * inv;
}

// ---------------------------------------------------------------------------
// Phase 2: recompute S in 16-row K-chunks, p = exp(s*a - m_t)*f_t, write final
// prob once + accumulate P@V. 128 threads, warps 2x2. Q resident.
// Barrier schedule (race-fixed): end-of-iteration barrier guarantees all
// warps finished reading Ks/Vs[buf] and Ps before the next iteration's
// prefetch/writes touch them.
// ---------------------------------------------------------------------------
#define PSP 20
#define OFF_QS 0                        // [128][68]
#define OFF_KS (OFF_QS + 128*68)        // [2][16][68]
#define OFF_VS (OFF_KS + 2*16*68)       // [2][16][72] (uint bits)
#define OFF_PS (OFF_VS + 2*16*72)       // [128][PSP]  (uint bits)
#define F2_SMEM ((OFF_PS + 128*PSP) * 4)  // 62976 bytes

__global__ __launch_bounds__(128, 3) void attn_fused2(float* __restrict__ score)
{
    extern __shared__ float sm[];
    float    (*Qs)[68]     = (float (*)[68])(sm + OFF_QS);
    float    (*Ks)[16][68] = (float (*)[16][68])(sm + OFF_KS);
    unsigned (*Vs)[16][72] = (unsigned (*)[16][72])(sm + OFF_VS);
    unsigned (*Ps)[PSP]    = (unsigned (*)[PSP])(sm + OFF_PS);

    int tid = threadIdx.x;
    int warp = tid >> 5, lane = tid & 31;
    int wm = warp >> 1, wn = warp & 1;
    int grp = lane >> 2, qd = lane & 3;
    int bh = blockIdx.y, b = bh >> 4, h = bh & 15;
    int qt = blockIdx.x;

    const float* qb = g_q + (size_t)b * SEQ * DIM + (size_t)(qt * 128) * DIM + h * DK;
    const float* kb = g_k + (size_t)b * SEQ * DIM + h * DK;
    const float* vb = g_v + (size_t)b * SEQ * DIM + h * DK;
    float* ob = score + (size_t)bh * SEQ * SEQ + (size_t)(qt * 128) * SEQ;

    // preload Q tile (128x64) + K/V chunk 0
    #pragma unroll
    for (int i = 0; i < 16; i++) {
        int id = tid + i * 128;
        int r  = id >> 4;
        int c4 = (id & 15) << 2;
        cpa16(&Qs[r][c4], qb + (size_t)r * DIM + c4);
    }
    #pragma unroll
    for (int i = 0; i < 2; i++) {
        int id = tid + i * 128;
        int r  = id >> 4;
        int c4 = (id & 15) << 2;
        cpa16(&Ks[0][r][c4], kb + (size_t)r * DIM + c4);
        cpa16(&Vs[0][r][c4], vb + (size_t)r * DIM + c4);
    }
    CPA_COMMIT();
    CPA_WAIT0();
    __syncthreads();

    float acc[4][4][4] = {};
    float m_r[4][2], f_r[4][2];
    int buf = 0;
    const float alpha = 0.125f;

    for (int t = 0; t < 128; t++) {
        // prefetch next chunk into the OTHER buffer.
        // Safe: end-of-previous-iteration barrier ensures nobody still reads it.
        if (t + 1 < 128) {
            int nb = buf ^ 1;
            #pragma unroll
            for (int i = 0; i < 2; i++) {
                int id = tid + i * 128;
                int r  = id >> 4;
                int c4 = (id & 15) << 2;
                cpa16(&Ks[nb][r][c4], kb + (size_t)((t + 1) * 16 + r) * DIM + c4);
                cpa16(&Vs[nb][r][c4], vb + (size_t)((t + 1) * 16 + r) * DIM + c4);
            }
            CPA_COMMIT();
        }
        if ((t & 7) == 0) {
            int ct = t >> 3;
            #pragma unroll
            for (int mi = 0; mi < 4; mi++) {
                #pragma unroll
                for (int hf = 0; hf < 2; hf++) {
                    int row = qt * 128 + wm * 64 + mi * 16 + hf * 8 + grp;
                    size_t idx = ((size_t)(bh << 11) + row) * NCT + ct;
                    m_r[mi][hf] = g_smax[idx];
                    f_r[mi][hf] = g_factor[idx];
                }
            }
        }

        // QK: S chunk [128 x 16]
        float sacc[4][4] = {};
        #pragma unroll
        for (int kk8 = 0; kk8 < 64; kk8 += 8) {
            unsigned a[4][4], bb[2];
            #pragma unroll
            for (int mi = 0; mi < 4; mi++) {
                int m = wm * 64 + mi * 16;
                a[mi][0] = __float_as_uint(Qs[m + grp    ][kk8 + qd    ]);
                a[mi][1] = __float_as_uint(Qs[m + grp + 8][kk8 + qd    ]);
                a[mi][2] = __float_as_uint(Qs[m + grp    ][kk8 + qd + 4]);
                a[mi][3] = __float_as_uint(Qs[m + grp + 8][kk8 + qd + 4]);
            }
            {
                int n = wn * 8 + grp;
                bb[0] = __float_as_uint(Ks[buf][n][kk8 + qd    ]);
                bb[1] = __float_as_uint(Ks[buf][n][kk8 + qd + 4]);
            }
            #pragma unroll
            for (int mi = 0; mi < 4; mi++)
                mma_tf32(sacc[mi], a[mi][0], a[mi][1], a[mi][2], a[mi][3],
                         bb[0], bb[1]);
        }

        // p = exp(s*alpha - m_t) * f_t  (mul-then-sub mirrors phase 1)
        float p[4][4];
        #pragma unroll
        for (int mi = 0; mi < 4; mi++) {
            float s0 = sacc[mi][0] * alpha, s1 = sacc[mi][1] * alpha;
            float s2 = sacc[mi][2] * alpha, s3 = sacc[mi][3] * alpha;
            p[mi][0] = __expf(s0 - m_r[mi][0]) * f_r[mi][0];
            p[mi][1] = __expf(s1 - m_r[mi][0]) * f_r[mi][0];
            p[mi][2] = __expf(s2 - m_r[mi][1]) * f_r[mi][1];
            p[mi][3] = __expf(s3 - m_r[mi][1]) * f_r[mi][1];
        }

        // write final prob (global) + stash tf32 bits in Ps.
        // Safe vs prior PV reads of Ps: end-of-previous-iteration barrier.
        int colL = wn * 8 + qd * 2;
        #pragma unroll
        for (int mi = 0; mi < 4; mi++) {
            int r0 = wm * 64 + mi * 16 + grp;
            *(float2*)(ob + (size_t)r0 * SEQ + t * 16 + colL) =
                make_float2(p[mi][0], p[mi][1]);
            *(float2*)(ob + (size_t)(r0 + 8) * SEQ + t * 16 + colL) =
                make_float2(p[mi][2], p[mi][3]);
            uint2 u0 = make_uint2(f2tf(p[mi][0]), f2tf(p[mi][1]));
            uint2 u1 = make_uint2(f2tf(p[mi][2]), f2tf(p[mi][3]));
            *(uint2*)&Ps[r0][colL]     = u0;
            *(uint2*)&Ps[r0 + 8][colL] = u1;
        }
        if (t + 1 < 128) CPA_WAIT0();
        __syncthreads();   // Ps visible to all warps; next K/V chunk landed

        // PV: acc += P_chunk[128x16] @ V_chunk[16x64]
        #pragma unroll
        for (int kk = 0; kk < 16; kk += 8) {
            unsigned a[4][4], bf[4][2];
            #pragma unroll
            for (int mi = 0; mi < 4; mi++) {
                int m = wm * 64 + mi * 16;
                a[mi][0] = Ps[m + grp    ][kk + qd    ];
                a[mi][1] = Ps[m + grp + 8][kk + qd    ];
                a[mi][2] = Ps[m + grp    ][kk + qd + 4];
                a[mi][3] = Ps[m + grp + 8][kk + qd + 4];
            }
            #pragma unroll
            for (int ni = 0; ni < 4; ni++) {
                int n = wn * 32 + ni * 8 + grp;
                bf[ni][0] = Vs[buf][kk + qd    ][n];
                bf[ni][1] = Vs[buf][kk + qd + 4][n];
            }
            #pragma unroll
            for (int mi = 0; mi < 4; mi++)
                #pragma unroll
                for (int ni = 0; ni < 4; ni++)
                    mma_tf32(acc[mi][ni], a[mi][0], a[mi][1], a[mi][2], a[mi][3],
                             bf[ni][0], bf[ni][1]);
        }
        __syncthreads();   // all reads of Ks/Vs[buf] and Ps done before next prefetch
        buf ^= 1;
    }

    float* obl = g_bl + (size_t)b * SEQ * DIM;
    int r0 = qt * 128 + wm * 64;
    int c0 = h * DK + wn * 32;
    #pragma unroll
    for (int mi = 0; mi < 4; mi++) {
        #pragma unroll
        for (int ni = 0; ni < 4; ni++) {
            int r  = r0 + mi * 16 + grp;
            int cc = c0 + ni * 8 + qd * 2;
            *(float2*)(obl + (size_t)r * DIM + cc) =
                make_float2(acc[mi][ni][0], acc[mi][ni][1]);
            *(float2*)(obl + (size_t)(r + 8) * DIM + cc) =
                make_float2(acc[mi][ni][2], acc[mi][ni][3]);
        }
    }
}

// ---------------------------------------------------------------------------
extern "C" void kernel_launch(void* const* d_in, const int* in_sizes, int n_in,
                              void* d_out, int out_size)
{
    const float* query = (const float*)d_in[0];
    const float* key   = (const float*)d_in[1];
    const float* value = (const float*)d_in[2];
    const float* Wq    = (const float*)d_in[3];
    const float* bq    = (const float*)d_in[4];
    const float* Wk    = (const float*)d_in[5];
    const float* bk    = (const float*)d_in[6];
    const float* Wv    = (const float*)d_in[7];
    const float* bv    = (const float*)d_in[8];
    const float* Wo    = (const float*)d_in[9];
    const float* bo    = (const float*)d_in[10];

    float* out   = (float*)d_out;                          // [B,S,D]
    float* score = out + (size_t)BSZ * SEQ * DIM;          // [B,H,S,S]

    float *pq, *pk, *pv, *pbl;
    cudaGetSymbolAddress((void**)&pq,  g_q);
    cudaGetSymbolAddress((void**)&pk,  g_k);
    cudaGetSymbolAddress((void**)&pv,  g_v);
    cudaGetSymbolAddress((void**)&pbl, g_bl);

    cudaFuncSetAttribute(gemm_cpa,
        cudaFuncAttributeMaxDynamicSharedMemorySize, GEMM_SMEM);
    cudaFuncSetAttribute(attn_stats,
        cudaFuncAttributeMaxDynamicSharedMemorySize, SC_SMEM);
    cudaFuncSetAttribute(attn_fused2,
        cudaFuncAttributeMaxDynamicSharedMemorySize, F2_SMEM);

    dim3 gp(DIM / 128, MTOT / 128);   // (8, 32)
    gemm_cpa<<<gp, 256, GEMM_SMEM>>>(query, Wq, bq, pq, MTOT, DIM, DIM, 1);
    gemm_cpa<<<gp, 256, GEMM_SMEM>>>(key,   Wk, bk, pk, MTOT, DIM, DIM, 1);
    gemm_cpa<<<gp, 256, GEMM_SMEM>>>(value, Wv, bv, pv, MTOT, DIM, DIM, 1);

    attn_stats<<<dim3(SEQ / 128, SEQ / 128, BH), 256, SC_SMEM>>>();
    combine_stats<<<NROWS / 256, 256>>>();
    attn_fused2<<<dim3(SEQ / 128, BH), 128, F2_SMEM>>>(score);

    gemm_cpa<<<gp, 256, GEMM_SMEM>>>(pbl, Wo, bo, out, MTOT, DIM, DIM, 0);
}